// round 11
// baseline (speedup 1.0000x reference)
#include <cuda_runtime.h>
#include <cuda_bf16.h>
#include <cstdint>

#define B_   8
#define N_   1024
#define M_   24576      // B_*3*N_
#define C2   256
#define H3   128
#define KNN_ 20
#define EPSF 1e-6f

typedef __nv_bfloat16 bf16;

// ---------------- scratch (allocation-free: __device__ globals) ----------------
__device__ float g_pc[B_*N_*3];
__device__ float g_m [B_*N_*3];
__device__ bf16  g_X0h[C2*M_], g_X0l[C2*M_];     // pos feats / netX, bf16 hi/lo planes
__device__ float g_DS[384*M_];                   // gemm1 out fp32: rows 0..255 = D, 256..383 = S
__device__ bf16  g_DSh[C2*M_], g_DSl[C2*M_];     // lrelu1 out pairs
__device__ bf16  g_Nth[H3*M_], g_Ntl[H3*M_];
__device__ float g_D1[H3*M_];
__device__ bf16  g_D1h[H3*M_], g_D1l[H3*M_];
__device__ float g_P [H3*24];
__device__ float g_Wcat[5*384*C2];
__device__ float g_Badd[384*24];
__device__ bf16  g_WcatH[5*384*C2], g_WcatL[5*384*C2];
__device__ bf16  g_W01H[5*C2*C2],   g_W01L[5*C2*C2];   // [W0 ; Wd1@W0] pairs per block
__device__ bf16  g_W1H[5*H3*H3],    g_W1L[5*H3*H3];

// ---------------- helpers ----------------
__device__ __forceinline__ void split_bf(float x, bf16& h, bf16& l) {
    h = __float2bfloat16_rn(x);
    l = __float2bfloat16_rn(x - __bfloat162float(h));
}
__device__ __forceinline__ void cp16g(void* smem, const void* g) {
    uint32_t s = (uint32_t)__cvta_generic_to_shared(smem);
    asm volatile("cp.async.cg.shared.global [%0], [%1], 16;" :: "r"(s), "l"(g));
}
__device__ __forceinline__ uint32_t scvt(const void* p) {
    return (uint32_t)__cvta_generic_to_shared(p);
}
__device__ __forceinline__ void ldsm4(uint32_t* r, uint32_t a) {
    asm volatile("ldmatrix.sync.aligned.m8n8.x4.shared.b16 {%0,%1,%2,%3}, [%4];"
        : "=r"(r[0]), "=r"(r[1]), "=r"(r[2]), "=r"(r[3]) : "r"(a));
}
__device__ __forceinline__ void ldsm4t(uint32_t* r, uint32_t a) {
    asm volatile("ldmatrix.sync.aligned.m8n8.x4.trans.shared.b16 {%0,%1,%2,%3}, [%4];"
        : "=r"(r[0]), "=r"(r[1]), "=r"(r[2]), "=r"(r[3]) : "r"(a));
}
__device__ __forceinline__ void mma16(float* c, const uint32_t* a, const uint32_t* b) {
    asm volatile("mma.sync.aligned.m16n8k16.row.col.f32.bf16.bf16.f32 "
        "{%0,%1,%2,%3}, {%4,%5,%6,%7}, {%8,%9}, {%0,%1,%2,%3};"
        : "+f"(c[0]), "+f"(c[1]), "+f"(c[2]), "+f"(c[3])
        : "r"(a[0]), "r"(a[1]), "r"(a[2]), "r"(a[3]), "r"(b[0]), "r"(b[1]));
}

// ---------------- 1. fused center + KNN -> mean of neighbor coords ----------------
__global__ void knn_center_kernel(const float* __restrict__ p) {
    int b     = blockIdx.x >> 2;
    int chunk = blockIdx.x & 3;
    __shared__ float sp[N_*3];
    __shared__ float sxx[N_];
    __shared__ float red[3][256];
    int tid = threadIdx.x;
    for (int t = tid; t < N_*3; t += 256) sp[t] = p[b*N_*3 + t];
    __syncthreads();
    float s0 = 0.f, s1 = 0.f, s2 = 0.f;
    for (int n = tid; n < N_; n += 256) {
        s0 += sp[n*3]; s1 += sp[n*3+1]; s2 += sp[n*3+2];
    }
    red[0][tid] = s0; red[1][tid] = s1; red[2][tid] = s2;
    __syncthreads();
    for (int st = 128; st > 0; st >>= 1) {
        if (tid < st) {
            red[0][tid] += red[0][tid + st];
            red[1][tid] += red[1][tid + st];
            red[2][tid] += red[2][tid + st];
        }
        __syncthreads();
    }
    float m0 = red[0][0] / N_, m1 = red[1][0] / N_, m2 = red[2][0] / N_;
    for (int n = tid; n < N_; n += 256) {
        float x = sp[n*3] - m0, y = sp[n*3+1] - m1, z = sp[n*3+2] - m2;
        sp[n*3] = x; sp[n*3+1] = y; sp[n*3+2] = z;
        if (chunk == 0) {
            float* o = g_pc + (size_t)(b*N_ + n)*3;
            o[0] = x; o[1] = y; o[2] = z;
        }
    }
    __syncthreads();
    for (int t = tid; t < N_; t += 256) {
        float x = sp[t*3], y = sp[t*3+1], z = sp[t*3+2];
        sxx[t] = x*x + y*y + z*z;
    }
    __syncthreads();

    int i = chunk*256 + tid;
    float xi = sp[i*3], yi = sp[i*3+1], zi = sp[i*3+2];
    float xxi = sxx[i];

    float bd[KNN_]; int bi[KNN_];
#pragma unroll
    for (int t = 0; t < KNN_; t++) { bd[t] = -3.4e38f; bi[t] = 0; }

    for (int j = 0; j < N_; j++) {
        float dot = xi*sp[j*3] + yi*sp[j*3+1] + zi*sp[j*3+2];
        float nd  = 2.f*dot - xxi - sxx[j];
        if (nd > bd[KNN_-1]) {                      // strict > => ties keep lower index
            int t = KNN_-1;
            while (t > 0 && bd[t-1] < nd) { bd[t] = bd[t-1]; bi[t] = bi[t-1]; t--; }
            bd[t] = nd; bi[t] = j;
        }
    }
    float a0 = 0.f, a1 = 0.f, a2 = 0.f;
#pragma unroll
    for (int t = 0; t < KNN_; t++) {
        int j = bi[t];
        a0 += sp[j*3]; a1 += sp[j*3+1]; a2 += sp[j*3+2];
    }
    float* o = g_m + (size_t)(b*N_ + i)*3;
    o[0] = a0 / KNN_; o[1] = a1 / KNN_; o[2] = a2 / KNN_;
}

// ---------------- 2. fused edge-feature + W_pos + pool_k -> X0 hi/lo ----------------
__global__ void featpos_kernel(const float* __restrict__ Wpos) {
    int bk = blockIdx.x;                 // b(8) * v(3) * chunk(8)
    int b = bk / 24; int rem = bk % 24;
    int v = rem / 8; int chunk = rem % 8;
    int n0 = chunk * 128;
    __shared__ float f0[128], f1[128], f2[128];
    if (threadIdx.x < 128) {
        int n = n0 + threadIdx.x;
        const float* pp = g_pc + (size_t)(b*N_ + n)*3;
        const float* mm = g_m  + (size_t)(b*N_ + n)*3;
        float p0 = pp[0], p1 = pp[1], p2 = pp[2];
        float m0 = mm[0], m1 = mm[1], m2 = mm[2];
        float pv = (v == 0) ? p0 : ((v == 1) ? p1 : p2);
        float mv = (v == 0) ? m0 : ((v == 1) ? m1 : m2);
        float cv;
        if (v == 0)      cv = m1*p2 - m2*p1;
        else if (v == 1) cv = m2*p0 - m0*p2;
        else             cv = m0*p1 - m1*p0;
        f0[threadIdx.x] = mv - pv;
        f1[threadIdx.x] = pv;
        f2[threadIdx.x] = cv;
    }
    __syncthreads();
    int nl = threadIdx.x & 127;
    int oo = threadIdx.x >> 7;
    size_t colbase = (size_t)(b*3 + v)*N_ + n0;
    for (int ob = 0; ob < C2; ob += 2) {
        int o = ob + oo;
        float w0 = Wpos[o*3], w1 = Wpos[o*3+1], w2 = Wpos[o*3+2];
        float val = w0*f0[nl] + w1*f1[nl] + w2*f2[nl];
        size_t idx = (size_t)o*M_ + colbase + nl;
        bf16 h, l; split_bf(val, h, l);
        g_X0h[idx] = h; g_X0l[idx] = l;
    }
}

// ---------------- 3. ALL weight prep in one launch ----------------
// ranges: [0, 491520)           Wcat = [Wd0;Ws]: fp32 + pairs
//         [491520, 573440)      W1 pairs
//         [573440, 901120)      W01 = [W0 ; Wd1@W0] pairs
__global__ void wprep_kernel(const float* __restrict__ Wd0s, const float* __restrict__ Wss,
                             const float* __restrict__ W0s, const float* __restrict__ Wd1s,
                             const float* __restrict__ W1s) {
    int idx = blockIdx.x * 256 + threadIdx.x;
    const int R0 = 5*384*C2;            // 491520
    const int R1 = R0 + 5*H3*H3;        // 573440
    bf16 h, l;
    if (idx < R0) {
        int i   = idx / (384*C2);
        int rem = idx % (384*C2);
        int r = rem / C2, c = rem % C2;
        float v = (r < C2) ? Wd0s[(size_t)i*C2*C2 + r*C2 + c]
                           : Wss [(size_t)i*H3*C2 + (r - C2)*C2 + c];
        g_Wcat[idx] = v;
        split_bf(v, h, l);
        g_WcatH[idx] = h; g_WcatL[idx] = l;
    } else if (idx < R1) {
        int j = idx - R0;
        split_bf(W1s[j], h, l);
        g_W1H[j] = h; g_W1L[j] = l;
    } else {
        int j = idx - R1;                // 5*256*256
        int i = j >> 16;
        int rem = j & 65535;
        int r = rem >> 8, c = rem & 255;
        float v;
        if (r < H3) {
            v = W0s[(size_t)i*H3*C2 + r*C2 + c];
        } else {
            v = 0.f;
            const float* wd1 = Wd1s + (size_t)i*H3*H3 + (r - H3)*H3;
            const float* w0  = W0s  + (size_t)i*H3*C2 + c;
#pragma unroll 8
            for (int k = 0; k < H3; k++) v += wd1[k] * w0[(size_t)k*C2];
        }
        split_bf(v, h, l);
        g_W01H[j] = h; g_W01L[j] = l;
    }
}

// ---------------- 3d. Badd[384][24] = Wcat[:,128:] @ P ----------------
__global__ void badd_kernel(const float* __restrict__ Wcat) {
    int idx = blockIdx.x * 256 + threadIdx.x;   // 9216
    if (idx >= 384*24) return;
    int r = idx / 24, cg = idx % 24;
    float s = 0.f;
#pragma unroll 8
    for (int k = 0; k < H3; k++)
        s += Wcat[r*C2 + H3 + k] * g_P[k*24 + cg];
    g_Badd[idx] = s;
}

// ---------------- 4. bf16x3 tensor-core GEMM: Y = A @ B ----------------
// block tile 128(M) x 64(N), BK=16, 3-stage cp.async pipeline, 8 warps (4x2)
// A smem: stride 16 elems (32B) with 16B-granule XOR swizzle (cp.async dest aligned,
// ldmatrix conflict-free). 3-term compensation: ah*bh + ah*bl + al*bh.
// mode 0: Yf fp32 (if set) else Yh/Yl pairs.  mode 1 (split): rows<128 -> pairs,
// rows>=128 -> Yf fp32 at row-128.  Optional fused point-mean pool into Psum.
__global__ __launch_bounds__(256, 2)
void gemm_bfx3_kernel(const bf16* __restrict__ Ah, const bf16* __restrict__ Al, int lda,
                      const bf16* __restrict__ Bh, const bf16* __restrict__ Bl,
                      float* __restrict__ Yf, bf16* __restrict__ Yh, bf16* __restrict__ Yl,
                      int K, const float* __restrict__ Badd, const float* __restrict__ Add,
                      float* __restrict__ Psum, int mode)
{
    const int SA = 16, SB = 72;        // A: 32B stride + swizzle; B: 144B padded stride
    __shared__ bf16 sAh[3][128*SA], sAl[3][128*SA];
    __shared__ bf16 sBh[3][16*SB],  sBl[3][16*SB];
    int tid = threadIdx.x, lane = tid & 31, wid = tid >> 5;
    int warp_m = wid >> 1, warp_n = wid & 1;
    int gid = lane >> 2, tig = lane & 3;
    int nBase = blockIdx.x * 64, oBase = blockIdx.y * 128;

    // loaders
    int aRow = tid >> 1, aG = tid & 1;
    int bRow = (tid & 127) >> 3, bSeg = (tid & 7) * 8;
    const bf16* Agh = Ah + (size_t)(oBase + aRow)*lda + aG*8;
    const bf16* Agl = Al + (size_t)(oBase + aRow)*lda + aG*8;
    const bool bHi = (tid < 128);
    const bf16* Bg = (bHi ? Bh : Bl) + (size_t)bRow*M_ + nBase + bSeg;
    int aOffSm = aRow*SA + ((aG ^ ((aRow >> 2) & 1)) << 3);   // swizzled dest (elements)
    int bOffSm = bRow*SB + bSeg;

    // ldmatrix lane offsets (bytes)
    int selA = ((lane >> 3) & 1) * 8 + (lane & 7);   // row within 16
    int halfA = lane >> 4;                           // k-half (0/1)
    uint32_t aOff[2];
#pragma unroll
    for (int mt = 0; mt < 2; mt++) {
        int row = warp_m*32 + mt*16 + selA;
        aOff[mt] = (uint32_t)((row*SA + ((halfA ^ ((row >> 2) & 1)) << 3)) * 2);
    }
    int selBk = ((lane >> 3) & 1) * 8 + (lane & 7);
    int selBn = (lane >> 4) * 8;
    uint32_t bOff[2];
#pragma unroll
    for (int nt2 = 0; nt2 < 2; nt2++)
        bOff[nt2] = (uint32_t)((selBk*SB + warp_n*32 + nt2*16 + selBn) * 2);

    uint32_t sAhB[3] = { scvt(sAh[0]), scvt(sAh[1]), scvt(sAh[2]) };
    uint32_t sAlB[3] = { scvt(sAl[0]), scvt(sAl[1]), scvt(sAl[2]) };
    uint32_t sBhB[3] = { scvt(sBh[0]), scvt(sBh[1]), scvt(sBh[2]) };
    uint32_t sBlB[3] = { scvt(sBl[0]), scvt(sBl[1]), scvt(sBl[2]) };

    int stages = K >> 4;
    float c[2][4][4];
#pragma unroll
    for (int mt = 0; mt < 2; mt++)
#pragma unroll
        for (int nt = 0; nt < 4; nt++)
#pragma unroll
            for (int r = 0; r < 4; r++) c[mt][nt][r] = 0.f;

#define LOAD_STAGE(s, buf)                                              \
    do {                                                                \
        int k0_ = (s) * 16;                                             \
        cp16g(&sAh[buf][aOffSm], Agh + k0_);                            \
        cp16g(&sAl[buf][aOffSm], Agl + k0_);                            \
        cp16g((bHi ? &sBh[buf][bOffSm] : &sBl[buf][bOffSm]),            \
              Bg + (size_t)k0_*M_);                                     \
        asm volatile("cp.async.commit_group;");                         \
    } while (0)

    LOAD_STAGE(0, 0);
    LOAD_STAGE(1, 1);

    for (int s = 0; s < stages; s++) {
        if (s == stages - 1) asm volatile("cp.async.wait_group 0;");
        else                 asm volatile("cp.async.wait_group 1;");
        __syncthreads();
        int buf = s % 3;
        if (s + 2 < stages) LOAD_STAGE(s + 2, (s + 2) % 3);

        uint32_t ah[2][4], al[2][4], bh[2][4], bl[2][4];
        ldsm4(ah[0], sAhB[buf] + aOff[0]);
        ldsm4(ah[1], sAhB[buf] + aOff[1]);
        ldsm4(al[0], sAlB[buf] + aOff[0]);
        ldsm4(al[1], sAlB[buf] + aOff[1]);
        ldsm4t(bh[0], sBhB[buf] + bOff[0]);
        ldsm4t(bh[1], sBhB[buf] + bOff[1]);
        ldsm4t(bl[0], sBlB[buf] + bOff[0]);
        ldsm4t(bl[1], sBlB[buf] + bOff[1]);

#pragma unroll
        for (int mt = 0; mt < 2; mt++)
#pragma unroll
            for (int nt = 0; nt < 4; nt++) {
                const uint32_t* bhf = &bh[nt >> 1][(nt & 1)*2];
                const uint32_t* blf = &bl[nt >> 1][(nt & 1)*2];
                float* cc = c[mt][nt];
                mma16(cc, ah[mt], bhf);   // hi*hi
                mma16(cc, ah[mt], blf);   // hi*lo
                mma16(cc, al[mt], bhf);   // lo*hi
            }
    }
#undef LOAD_STAGE

    int cg = nBase >> 10;   // column group (b*3+v); tile never straddles groups
    float ps0[2] = {0.f, 0.f}, ps1[2] = {0.f, 0.f};
#pragma unroll
    for (int mt = 0; mt < 2; mt++) {
#pragma unroll
        for (int nt = 0; nt < 4; nt++) {
            int r0 = oBase + warp_m*32 + mt*16 + gid;
            int r1 = r0 + 8;
            int col = nBase + warp_n*32 + nt*8 + tig*2;
            float* cc = c[mt][nt];
            float ba0 = 0.f, ba1 = 0.f;
            if (Badd) { ba0 = Badd[r0*24 + cg]; ba1 = Badd[r1*24 + cg]; }
            size_t p0 = (size_t)r0*M_ + col;
            size_t p1 = (size_t)r1*M_ + col;
            float o0 = cc[0] + ba0, o1 = cc[1] + ba0;
            float o2 = cc[2] + ba1, o3 = cc[3] + ba1;
            if (Add) {
                float2 t0 = *(const float2*)&Add[p0];
                float2 t1 = *(const float2*)&Add[p1];
                o0 += t0.x; o1 += t0.y; o2 += t1.x; o3 += t1.y;
            }
            ps0[mt] += o0 + o1;
            ps1[mt] += o2 + o3;
            bool pairsOut;
            if (mode == 1) pairsOut = (r0 < H3);
            else           pairsOut = (Yf == nullptr);
            if (pairsOut) {
                __nv_bfloat162 h0, l0, h1, l1;
                split_bf(o0, h0.x, l0.x); split_bf(o1, h0.y, l0.y);
                split_bf(o2, h1.x, l1.x); split_bf(o3, h1.y, l1.y);
                *(__nv_bfloat162*)&Yh[p0] = h0;
                *(__nv_bfloat162*)&Yl[p0] = l0;
                *(__nv_bfloat162*)&Yh[p1] = h1;
                *(__nv_bfloat162*)&Yl[p1] = l1;
            } else {
                size_t q0 = p0, q1 = p1;
                if (mode == 1) { q0 = (size_t)(r0 - H3)*M_ + col; q1 = (size_t)(r1 - H3)*M_ + col; }
                *(float2*)&Yf[q0] = make_float2(o0, o1);
                *(float2*)&Yf[q1] = make_float2(o2, o3);
            }
        }
    }
    if (Psum) {
        const float invN = 1.f / N_;
#pragma unroll
        for (int mt = 0; mt < 2; mt++) {
            float a = ps0[mt], b2 = ps1[mt];
            a  += __shfl_xor_sync(0xffffffffu, a, 1);
            a  += __shfl_xor_sync(0xffffffffu, a, 2);
            b2 += __shfl_xor_sync(0xffffffffu, b2, 1);
            b2 += __shfl_xor_sync(0xffffffffu, b2, 2);
            if (tig == 0) {
                int r0 = oBase + warp_m*32 + mt*16 + gid;
                atomicAdd(&Psum[r0*24 + cg], a * invN);
                atomicAdd(&Psum[(r0 + 8)*24 + cg], b2 * invN);
            }
        }
    }
}

// ---------------- 5. VN leaky-relu: x from pairs (or P), d from fp32; out pairs --------
// Optionally zeroes Pzero[0..H3*24) (for the fused pool of the NEXT gemm).
__global__ void lrelu_kernel(const bf16* __restrict__ Xh, const bf16* __restrict__ Xl,
                             const float* __restrict__ P, const float* __restrict__ Dsrc,
                             bf16* __restrict__ Dh, bf16* __restrict__ Dl,
                             float* __restrict__ Pzero) {
    int idx = blockIdx.x * 256 + threadIdx.x;
    if (Pzero && idx < H3*24) Pzero[idx] = 0.f;
    int c = idx >> 13;
    int r = idx & 8191;
    int b = r >> 10, n = r & 1023;
    size_t base = (size_t)c*M_ + (size_t)b*3*N_ + n;
    float x0, x1, x2;
    if (P != nullptr && c >= H3) {
        int pc = (c - H3)*24 + b*3;
        x0 = P[pc]; x1 = P[pc + 1]; x2 = P[pc + 2];
    } else {
        x0 = __bfloat162float(Xh[base])        + __bfloat162float(Xl[base]);
        x1 = __bfloat162float(Xh[base + N_])   + __bfloat162float(Xl[base + N_]);
        x2 = __bfloat162float(Xh[base + 2*N_]) + __bfloat162float(Xl[base + 2*N_]);
    }
    float d0 = Dsrc[base], d1 = Dsrc[base + N_], d2 = Dsrc[base + 2*N_];
    float o0 = x0, o1 = x1, o2 = x2;
    float dot = x0*d0 + x1*d1 + x2*d2;
    if (dot < 0.f) {
        float dd = d0*d0 + d1*d1 + d2*d2;
        float s = dot / (dd + EPSF);
        o0 = x0 - s*d0; o1 = x1 - s*d1; o2 = x2 - s*d2;
    }
    bf16 h, l;
    split_bf(o0, h, l); Dh[base]        = h; Dl[base]        = l;
    split_bf(o1, h, l); Dh[base + N_]   = h; Dl[base + N_]   = l;
    split_bf(o2, h, l); Dh[base + 2*N_] = h; Dl[base + 2*N_] = l;
}

// ---------------- 7. head ----------------
__global__ void final_kernel(const float* __restrict__ Wd, const float* __restrict__ Wc,
                             float* __restrict__ out) {
    __shared__ float s_net[H3*24];
    __shared__ float s_act[H3*24];
    int o = threadIdx.x;
    for (int t = o; t < H3*24; t += 128) s_net[t] = g_P[t];
    __syncthreads();

    float dcol[24];
#pragma unroll
    for (int col = 0; col < 24; col++) dcol[col] = 0.f;
    for (int i = 0; i < H3; i++) {
        float w = Wd[o*H3 + i];
#pragma unroll
        for (int col = 0; col < 24; col++) dcol[col] += w * s_net[i*24 + col];
    }
#pragma unroll
    for (int b = 0; b < 8; b++) {
        float x0 = s_net[o*24 + b*3], x1 = s_net[o*24 + b*3 + 1], x2 = s_net[o*24 + b*3 + 2];
        float d0 = dcol[b*3], d1 = dcol[b*3 + 1], d2 = dcol[b*3 + 2];
        float dot = x0*d0 + x1*d1 + x2*d2;
        float a0 = x0, a1 = x1, a2 = x2;
        if (dot < 0.f) {
            float dd = d0*d0 + d1*d1 + d2*d2;
            float s = dot / (dd + EPSF);
            a0 = x0 - s*d0; a1 = x1 - s*d1; a2 = x2 - s*d2;
        }
        s_act[o*24 + b*3] = a0; s_act[o*24 + b*3 + 1] = a1; s_act[o*24 + b*3 + 2] = a2;
    }
    __syncthreads();

    float oc[24];
#pragma unroll
    for (int col = 0; col < 24; col++) oc[col] = 0.f;
    for (int i = 0; i < H3; i++) {
        float w = Wc[o*H3 + i];
#pragma unroll
        for (int col = 0; col < 24; col++) oc[col] += w * s_act[i*24 + col];
    }
#pragma unroll
    for (int col = 0; col < 24; col++) {
        int b = col / 3, v = col % 3;
        out[b*384 + o*3 + v] = oc[col];
    }
}

// ---------------- host ----------------
static float* symaddrf(const void* sym) {
    void* p = nullptr; cudaGetSymbolAddress(&p, sym); return (float*)p;
}
static bf16* symaddrb(const void* sym) {
    void* p = nullptr; cudaGetSymbolAddress(&p, sym); return (bf16*)p;
}

extern "C" void kernel_launch(void* const* d_in, const int* in_sizes, int n_in,
                              void* d_out, int out_size) {
    const float* p      = (const float*)d_in[0];
    const float* Wpos   = (const float*)d_in[1];
    const float* Wd0s   = (const float*)d_in[2];
    const float* W0s    = (const float*)d_in[3];
    const float* Wd1s   = (const float*)d_in[4];
    const float* W1s    = (const float*)d_in[5];
    const float* Wss    = (const float*)d_in[6];
    const float* Wd_act = (const float*)d_in[7];
    const float* Wc     = (const float*)d_in[8];
    float* out = (float*)d_out;

    float* DS    = symaddrf(g_DS);
    float* S     = DS + (size_t)C2*M_;
    float* D1    = symaddrf(g_D1);
    float* Wcat  = symaddrf(g_Wcat);
    float* Badd  = symaddrf(g_Badd);
    float* P     = symaddrf(g_P);
    bf16 *X0h = symaddrb(g_X0h), *X0l = symaddrb(g_X0l);
    bf16 *DSh = symaddrb(g_DSh), *DSl = symaddrb(g_DSl);
    bf16 *Nth = symaddrb(g_Nth), *Ntl = symaddrb(g_Ntl);
    bf16 *D1h = symaddrb(g_D1h), *D1l = symaddrb(g_D1l);
    bf16 *WcH = symaddrb(g_WcatH), *WcL = symaddrb(g_WcatL);
    bf16 *W01H = symaddrb(g_W01H), *W01L = symaddrb(g_W01L);
    bf16 *W1H = symaddrb(g_W1H),   *W1L = symaddrb(g_W1L);

    knn_center_kernel<<<B_*4, 256>>>(p);                 // launch 1
    featpos_kernel<<<B_*3*8, 256>>>(Wpos);               // launch 2
    wprep_kernel<<<3520, 256>>>(Wd0s, Wss, W0s, Wd1s, W1s);  // launch 3

    for (int i = 0; i < 5; i++) {
        size_t oc2 = (size_t)i*384*C2;
        const bf16* WciH = WcH + oc2; const bf16* WciL = WcL + oc2;
        const bf16* W01iH = W01H + (size_t)i*C2*C2; const bf16* W01iL = W01L + (size_t)i*C2*C2;
        const bf16* W1iH = W1H + (size_t)i*H3*H3;   const bf16* W1iL = W1L + (size_t)i*H3*H3;

        if (i == 0) {
            // D;S = [Wd0;Ws] @ X0  (K=256)                  -- launch 4: ncu target
            gemm_bfx3_kernel<<<dim3(384, 3), 256>>>(WciH, WciL, C2, X0h, X0l,
                DS, nullptr, nullptr, C2, nullptr, nullptr, nullptr, 0);
        } else {
            badd_kernel<<<36, 256>>>(Wcat + oc2);
            gemm_bfx3_kernel<<<dim3(384, 3), 256>>>(WciH, WciL, C2, X0h, X0l,
                DS, nullptr, nullptr, H3, Badd, nullptr, nullptr, 0);
        }
        // D' = lrelu(X, D) -> pairs (256 ch; for i>0 channels 128..255 x comes from P)
        lrelu_kernel<<<(C2*8192)/256, 256>>>(X0h, X0l, (i == 0) ? nullptr : P, DS,
                                             DSh, DSl, nullptr);
        // [net ; d1] = [W0 ; Wd1@W0] @ D'  (K=256): rows<128 -> Nt pairs, rows>=128 -> D1 fp32
        gemm_bfx3_kernel<<<dim3(384, 2), 256>>>(W01iH, W01iL, C2, DSh, DSl,
            D1, Nth, Ntl, C2, nullptr, nullptr, nullptr, 1);
        // D1' = lrelu(Nt, D1) -> pairs (128 ch); zeroes P for the fused pool below
        lrelu_kernel<<<(H3*8192)/256, 256>>>(Nth, Ntl, nullptr, D1, D1h, D1l, P);
        // netX = W1 @ D1' + S (K=128) -> pairs into X0; fused pool accumulates P
        gemm_bfx3_kernel<<<dim3(384, 1), 256>>>(W1iH, W1iL, H3, D1h, D1l,
            nullptr, X0h, X0l, H3, nullptr, S, P, 0);
    }

    final_kernel<<<1, 128>>>(Wd_act, Wc, out);
}

// round 12
// speedup vs baseline: 1.0333x; 1.0333x over previous
#include <cuda_runtime.h>
#include <cuda_bf16.h>
#include <cstdint>

#define B_   8
#define N_   1024
#define M_   24576      // B_*3*N_
#define C2   256
#define H3   128
#define KNN_ 20
#define EPSF 1e-6f

typedef __nv_bfloat16 bf16;

// ---------------- scratch (allocation-free: __device__ globals) ----------------
__device__ float g_pc[B_*N_*3];
__device__ float g_m [B_*N_*3];
__device__ bf16  g_X0h[C2*M_], g_X0l[C2*M_];     // pos feats / netX, bf16 hi/lo planes
__device__ float g_DS[384*M_];                   // gemm1 out fp32: rows 0..255 = D, 256..383 = S
__device__ bf16  g_DSh[C2*M_], g_DSl[C2*M_];     // lrelu1 out pairs
__device__ bf16  g_Nth[H3*M_], g_Ntl[H3*M_];
__device__ float g_D1[H3*M_];
__device__ bf16  g_D1h[H3*M_], g_D1l[H3*M_];
__device__ float g_P [H3*24];
__device__ float g_Wcat[5*384*C2];
__device__ float g_Badd[384*24];
__device__ bf16  g_WcatH[5*384*C2], g_WcatL[5*384*C2];
__device__ bf16  g_W0H[5*H3*C2],    g_W0L[5*H3*C2];
__device__ bf16  g_Wd1H[5*H3*H3],   g_Wd1L[5*H3*H3];
__device__ bf16  g_W1H[5*H3*H3],    g_W1L[5*H3*H3];

// ---------------- helpers ----------------
__device__ __forceinline__ void split_bf(float x, bf16& h, bf16& l) {
    h = __float2bfloat16_rn(x);
    l = __float2bfloat16_rn(x - __bfloat162float(h));
}
__device__ __forceinline__ void cp16g(void* smem, const void* g) {
    uint32_t s = (uint32_t)__cvta_generic_to_shared(smem);
    asm volatile("cp.async.cg.shared.global [%0], [%1], 16;" :: "r"(s), "l"(g));
}
__device__ __forceinline__ uint32_t scvt(const void* p) {
    return (uint32_t)__cvta_generic_to_shared(p);
}
__device__ __forceinline__ void ldsm4(uint32_t* r, uint32_t a) {
    asm volatile("ldmatrix.sync.aligned.m8n8.x4.shared.b16 {%0,%1,%2,%3}, [%4];"
        : "=r"(r[0]), "=r"(r[1]), "=r"(r[2]), "=r"(r[3]) : "r"(a));
}
__device__ __forceinline__ void ldsm4t(uint32_t* r, uint32_t a) {
    asm volatile("ldmatrix.sync.aligned.m8n8.x4.trans.shared.b16 {%0,%1,%2,%3}, [%4];"
        : "=r"(r[0]), "=r"(r[1]), "=r"(r[2]), "=r"(r[3]) : "r"(a));
}
__device__ __forceinline__ void mma16(float* c, const uint32_t* a, const uint32_t* b) {
    asm volatile("mma.sync.aligned.m16n8k16.row.col.f32.bf16.bf16.f32 "
        "{%0,%1,%2,%3}, {%4,%5,%6,%7}, {%8,%9}, {%0,%1,%2,%3};"
        : "+f"(c[0]), "+f"(c[1]), "+f"(c[2]), "+f"(c[3])
        : "r"(a[0]), "r"(a[1]), "r"(a[2]), "r"(a[3]), "r"(b[0]), "r"(b[1]));
}

// ---------------- 1. fused center + KNN -> mean of neighbor coords ----------------
__global__ void knn_center_kernel(const float* __restrict__ p) {
    int b     = blockIdx.x >> 2;
    int chunk = blockIdx.x & 3;
    __shared__ float sp[N_*3];
    __shared__ float sxx[N_];
    __shared__ float red[3][256];
    int tid = threadIdx.x;
    for (int t = tid; t < N_*3; t += 256) sp[t] = p[b*N_*3 + t];
    __syncthreads();
    float s0 = 0.f, s1 = 0.f, s2 = 0.f;
    for (int n = tid; n < N_; n += 256) {
        s0 += sp[n*3]; s1 += sp[n*3+1]; s2 += sp[n*3+2];
    }
    red[0][tid] = s0; red[1][tid] = s1; red[2][tid] = s2;
    __syncthreads();
    for (int st = 128; st > 0; st >>= 1) {
        if (tid < st) {
            red[0][tid] += red[0][tid + st];
            red[1][tid] += red[1][tid + st];
            red[2][tid] += red[2][tid + st];
        }
        __syncthreads();
    }
    float m0 = red[0][0] / N_, m1 = red[1][0] / N_, m2 = red[2][0] / N_;
    for (int n = tid; n < N_; n += 256) {
        float x = sp[n*3] - m0, y = sp[n*3+1] - m1, z = sp[n*3+2] - m2;
        sp[n*3] = x; sp[n*3+1] = y; sp[n*3+2] = z;
        if (chunk == 0) {
            float* o = g_pc + (size_t)(b*N_ + n)*3;
            o[0] = x; o[1] = y; o[2] = z;
        }
    }
    __syncthreads();
    for (int t = tid; t < N_; t += 256) {
        float x = sp[t*3], y = sp[t*3+1], z = sp[t*3+2];
        sxx[t] = x*x + y*y + z*z;
    }
    __syncthreads();

    int i = chunk*256 + tid;
    float xi = sp[i*3], yi = sp[i*3+1], zi = sp[i*3+2];
    float xxi = sxx[i];

    float bd[KNN_]; int bi[KNN_];
#pragma unroll
    for (int t = 0; t < KNN_; t++) { bd[t] = -3.4e38f; bi[t] = 0; }

    for (int j = 0; j < N_; j++) {
        float dot = xi*sp[j*3] + yi*sp[j*3+1] + zi*sp[j*3+2];
        float nd  = 2.f*dot - xxi - sxx[j];
        if (nd > bd[KNN_-1]) {                      // strict > => ties keep lower index
            int t = KNN_-1;
            while (t > 0 && bd[t-1] < nd) { bd[t] = bd[t-1]; bi[t] = bi[t-1]; t--; }
            bd[t] = nd; bi[t] = j;
        }
    }
    float a0 = 0.f, a1 = 0.f, a2 = 0.f;
#pragma unroll
    for (int t = 0; t < KNN_; t++) {
        int j = bi[t];
        a0 += sp[j*3]; a1 += sp[j*3+1]; a2 += sp[j*3+2];
    }
    float* o = g_m + (size_t)(b*N_ + i)*3;
    o[0] = a0 / KNN_; o[1] = a1 / KNN_; o[2] = a2 / KNN_;
}

// ---------------- 2. fused edge-feature + W_pos + pool_k -> X0 hi/lo ----------------
__global__ void featpos_kernel(const float* __restrict__ Wpos) {
    int bk = blockIdx.x;                 // b(8) * v(3) * chunk(8)
    int b = bk / 24; int rem = bk % 24;
    int v = rem / 8; int chunk = rem % 8;
    int n0 = chunk * 128;
    __shared__ float f0[128], f1[128], f2[128];
    if (threadIdx.x < 128) {
        int n = n0 + threadIdx.x;
        const float* pp = g_pc + (size_t)(b*N_ + n)*3;
        const float* mm = g_m  + (size_t)(b*N_ + n)*3;
        float p0 = pp[0], p1 = pp[1], p2 = pp[2];
        float m0 = mm[0], m1 = mm[1], m2 = mm[2];
        float pv = (v == 0) ? p0 : ((v == 1) ? p1 : p2);
        float mv = (v == 0) ? m0 : ((v == 1) ? m1 : m2);
        float cv;
        if (v == 0)      cv = m1*p2 - m2*p1;
        else if (v == 1) cv = m2*p0 - m0*p2;
        else             cv = m0*p1 - m1*p0;
        f0[threadIdx.x] = mv - pv;
        f1[threadIdx.x] = pv;
        f2[threadIdx.x] = cv;
    }
    __syncthreads();
    int nl = threadIdx.x & 127;
    int oo = threadIdx.x >> 7;
    size_t colbase = (size_t)(b*3 + v)*N_ + n0;
    for (int ob = 0; ob < C2; ob += 2) {
        int o = ob + oo;
        float w0 = Wpos[o*3], w1 = Wpos[o*3+1], w2 = Wpos[o*3+2];
        float val = w0*f0[nl] + w1*f1[nl] + w2*f2[nl];
        size_t idx = (size_t)o*M_ + colbase + nl;
        bf16 h, l; split_bf(val, h, l);
        g_X0h[idx] = h; g_X0l[idx] = l;
    }
}

// ---------------- 3. ALL weight prep in one launch ----------------
// ranges: [0, 491520)  Wcat=[Wd0;Ws] fp32+pairs; [.., 655360) W0 pairs;
//         [.., 737280) Wd1 pairs; [.., 819200) W1 pairs
__global__ void wprep_kernel(const float* __restrict__ Wd0s, const float* __restrict__ Wss,
                             const float* __restrict__ W0s, const float* __restrict__ Wd1s,
                             const float* __restrict__ W1s) {
    int idx = blockIdx.x * 256 + threadIdx.x;
    const int R0 = 5*384*C2;            // 491520
    const int R1 = R0 + 5*H3*C2;        // 655360
    const int R2 = R1 + 5*H3*H3;        // 737280
    bf16 h, l;
    if (idx < R0) {
        int i   = idx / (384*C2);
        int rem = idx % (384*C2);
        int r = rem / C2, c = rem % C2;
        float v = (r < C2) ? Wd0s[(size_t)i*C2*C2 + r*C2 + c]
                           : Wss [(size_t)i*H3*C2 + (r - C2)*C2 + c];
        g_Wcat[idx] = v;
        split_bf(v, h, l);
        g_WcatH[idx] = h; g_WcatL[idx] = l;
    } else if (idx < R1) {
        int j = idx - R0;
        split_bf(W0s[j], h, l);  g_W0H[j] = h;  g_W0L[j] = l;
    } else if (idx < R2) {
        int j = idx - R1;
        split_bf(Wd1s[j], h, l); g_Wd1H[j] = h; g_Wd1L[j] = l;
    } else {
        int j = idx - R2;
        split_bf(W1s[j], h, l);  g_W1H[j] = h;  g_W1L[j] = l;
    }
}

// ---------------- 3d. Badd[384][24] = Wcat[:,128:] @ P ----------------
__global__ void badd_kernel(const float* __restrict__ Wcat) {
    int idx = blockIdx.x * 256 + threadIdx.x;   // 9216
    if (idx >= 384*24) return;
    int r = idx / 24, cg = idx % 24;
    float s = 0.f;
#pragma unroll 8
    for (int k = 0; k < H3; k++)
        s += Wcat[r*C2 + H3 + k] * g_P[k*24 + cg];
    g_Badd[idx] = s;
}

// ---------------- 4. bf16x3 tensor-core GEMM, 128x128 tile ----------------
// BM=128, BN=128, BK=16, 2-stage cp.async. 8 warps: warp_m(2) x warp_n(4),
// warp tile 64(M) x 32(N), A consumed in two mt-halves to cap live registers.
// A smem: 32B stride + 16B-granule XOR swizzle. B smem: [16][136] per plane.
// 3-term compensation: ah*bh + ah*bl + al*bh.
__global__ __launch_bounds__(256, 2)
void gemm_bfx3_kernel(const bf16* __restrict__ Ah, const bf16* __restrict__ Al, int lda,
                      const bf16* __restrict__ Bh, const bf16* __restrict__ Bl,
                      float* __restrict__ Yf, bf16* __restrict__ Yh, bf16* __restrict__ Yl,
                      int K, const float* __restrict__ Badd, const float* __restrict__ Add,
                      float* __restrict__ Psum)
{
    const int SA = 16, SB = 136;       // A: 32B stride+swizzle; B: 272B stride (16B mult)
    __shared__ bf16 sAh[2][128*SA], sAl[2][128*SA];
    __shared__ bf16 sBh[2][16*SB],  sBl[2][16*SB];
    int tid = threadIdx.x, lane = tid & 31, wid = tid >> 5;
    int warp_m = wid >> 2, warp_n = wid & 3;
    int gid = lane >> 2, tig = lane & 3;
    int nBase = blockIdx.x * 128, oBase = blockIdx.y * 128;

    // A loader: 256 segs of 8 elems per plane -> 1 per thread
    int aRow = tid >> 1, aG = tid & 1;
    const bf16* Agh = Ah + (size_t)(oBase + aRow)*lda + aG*8;
    const bf16* Agl = Al + (size_t)(oBase + aRow)*lda + aG*8;
    int aOffSm = aRow*SA + ((aG ^ ((aRow >> 2) & 1)) << 3);

    // B loader: per plane 16 rows x 16 segs = 256 segs; hi threads (tid<128) do 2, lo same
    const bool bHi = (tid < 128);
    int bs   = tid & 127;
    int bRow = bs >> 4, bC = (bs & 15) * 8;
    const bf16* Bg = (bHi ? Bh : Bl) + (size_t)bRow*M_ + nBase + bC;
    int bOff0 = bRow*SB + bC;
    int bOff1 = (bRow + 8)*SB + bC;

    // ldmatrix lane offsets
    int selA = ((lane >> 3) & 1) * 8 + (lane & 7);
    int halfA = lane >> 4;
    uint32_t aOff[4];
#pragma unroll
    for (int mt = 0; mt < 4; mt++) {
        int row = warp_m*64 + mt*16 + selA;
        aOff[mt] = (uint32_t)((row*SA + ((halfA ^ ((row >> 2) & 1)) << 3)) * 2);
    }
    int selBk = ((lane >> 3) & 1) * 8 + (lane & 7);
    int selBn = (lane >> 4) * 8;
    uint32_t bOff[2];
#pragma unroll
    for (int j = 0; j < 2; j++)
        bOff[j] = (uint32_t)((selBk*SB + warp_n*32 + j*16 + selBn) * 2);

    uint32_t sAhB[2] = { scvt(sAh[0]), scvt(sAh[1]) };
    uint32_t sAlB[2] = { scvt(sAl[0]), scvt(sAl[1]) };
    uint32_t sBhB[2] = { scvt(sBh[0]), scvt(sBh[1]) };
    uint32_t sBlB[2] = { scvt(sBl[0]), scvt(sBl[1]) };

    int stages = K >> 4;
    float c[4][4][4];
#pragma unroll
    for (int mt = 0; mt < 4; mt++)
#pragma unroll
        for (int nt = 0; nt < 4; nt++)
#pragma unroll
            for (int r = 0; r < 4; r++) c[mt][nt][r] = 0.f;

#define LOAD_STAGE(s, buf)                                              \
    do {                                                                \
        int k0_ = (s) * 16;                                             \
        cp16g(&sAh[buf][aOffSm], Agh + k0_);                            \
        cp16g(&sAl[buf][aOffSm], Agl + k0_);                            \
        bf16* bdst = bHi ? sBh[buf] : sBl[buf];                         \
        cp16g(bdst + bOff0, Bg + (size_t)k0_*M_);                       \
        cp16g(bdst + bOff1, Bg + (size_t)(k0_ + 8)*M_);                 \
        asm volatile("cp.async.commit_group;");                         \
    } while (0)

    LOAD_STAGE(0, 0);
    if (stages > 1) LOAD_STAGE(1, 1);

    for (int s = 0; s < stages; s++) {
        if (s == stages - 1) asm volatile("cp.async.wait_group 0;");
        else                 asm volatile("cp.async.wait_group 1;");
        __syncthreads();
        int buf = s & 1;

        uint32_t bh[2][4], bl[2][4];
        ldsm4t(bh[0], sBhB[buf] + bOff[0]);
        ldsm4t(bh[1], sBhB[buf] + bOff[1]);
        ldsm4t(bl[0], sBlB[buf] + bOff[0]);
        ldsm4t(bl[1], sBlB[buf] + bOff[1]);

#pragma unroll
        for (int h2 = 0; h2 < 2; h2++) {
            uint32_t ah[2][4], al[2][4];
            ldsm4(ah[0], sAhB[buf] + aOff[h2*2]);
            ldsm4(ah[1], sAhB[buf] + aOff[h2*2 + 1]);
            ldsm4(al[0], sAlB[buf] + aOff[h2*2]);
            ldsm4(al[1], sAlB[buf] + aOff[h2*2 + 1]);
#pragma unroll
            for (int m2 = 0; m2 < 2; m2++)
#pragma unroll
                for (int nt = 0; nt < 4; nt++) {
                    const uint32_t* bhf = &bh[nt >> 1][(nt & 1)*2];
                    const uint32_t* blf = &bl[nt >> 1][(nt & 1)*2];
                    float* cc = c[h2*2 + m2][nt];
                    mma16(cc, ah[m2], bhf);   // hi*hi
                    mma16(cc, ah[m2], blf);   // hi*lo
                    mma16(cc, al[m2], bhf);   // lo*hi
                }
        }
        __syncthreads();
        if (s + 2 < stages) LOAD_STAGE(s + 2, buf);
    }
#undef LOAD_STAGE

    int cg = nBase >> 10;   // column group (b*3+v); 128-tile never straddles groups
    float ps0[4] = {0.f, 0.f, 0.f, 0.f}, ps1[4] = {0.f, 0.f, 0.f, 0.f};
#pragma unroll
    for (int mt = 0; mt < 4; mt++) {
#pragma unroll
        for (int nt = 0; nt < 4; nt++) {
            int r0 = oBase + warp_m*64 + mt*16 + gid;
            int r1 = r0 + 8;
            int col = nBase + warp_n*32 + nt*8 + tig*2;
            float* cc = c[mt][nt];
            float ba0 = 0.f, ba1 = 0.f;
            if (Badd) { ba0 = Badd[r0*24 + cg]; ba1 = Badd[r1*24 + cg]; }
            size_t p0 = (size_t)r0*M_ + col;
            size_t p1 = (size_t)r1*M_ + col;
            float o0 = cc[0] + ba0, o1 = cc[1] + ba0;
            float o2 = cc[2] + ba1, o3 = cc[3] + ba1;
            if (Add) {
                float2 t0 = *(const float2*)&Add[p0];
                float2 t1 = *(const float2*)&Add[p1];
                o0 += t0.x; o1 += t0.y; o2 += t1.x; o3 += t1.y;
            }
            ps0[mt] += o0 + o1;
            ps1[mt] += o2 + o3;
            if (Yf) {
                *(float2*)&Yf[p0] = make_float2(o0, o1);
                *(float2*)&Yf[p1] = make_float2(o2, o3);
            } else {
                __nv_bfloat162 h0, l0, h1, l1;
                split_bf(o0, h0.x, l0.x); split_bf(o1, h0.y, l0.y);
                split_bf(o2, h1.x, l1.x); split_bf(o3, h1.y, l1.y);
                *(__nv_bfloat162*)&Yh[p0] = h0;
                *(__nv_bfloat162*)&Yl[p0] = l0;
                *(__nv_bfloat162*)&Yh[p1] = h1;
                *(__nv_bfloat162*)&Yl[p1] = l1;
            }
        }
    }
    if (Psum) {
        const float invN = 1.f / N_;
#pragma unroll
        for (int mt = 0; mt < 4; mt++) {
            float a = ps0[mt], b2 = ps1[mt];
            a  += __shfl_xor_sync(0xffffffffu, a, 1);
            a  += __shfl_xor_sync(0xffffffffu, a, 2);
            b2 += __shfl_xor_sync(0xffffffffu, b2, 1);
            b2 += __shfl_xor_sync(0xffffffffu, b2, 2);
            if (tig == 0) {
                int r0 = oBase + warp_m*64 + mt*16 + gid;
                atomicAdd(&Psum[r0*24 + cg], a * invN);
                atomicAdd(&Psum[(r0 + 8)*24 + cg], b2 * invN);
            }
        }
    }
}

// ---------------- 5. VN leaky-relu ----------------
__global__ void lrelu_kernel(const bf16* __restrict__ Xh, const bf16* __restrict__ Xl,
                             const float* __restrict__ P, const float* __restrict__ Dsrc,
                             bf16* __restrict__ Dh, bf16* __restrict__ Dl,
                             float* __restrict__ Pzero) {
    int idx = blockIdx.x * 256 + threadIdx.x;
    if (Pzero && idx < H3*24) Pzero[idx] = 0.f;
    int c = idx >> 13;
    int r = idx & 8191;
    int b = r >> 10, n = r & 1023;
    size_t base = (size_t)c*M_ + (size_t)b*3*N_ + n;
    float x0, x1, x2;
    if (P != nullptr && c >= H3) {
        int pc = (c - H3)*24 + b*3;
        x0 = P[pc]; x1 = P[pc + 1]; x2 = P[pc + 2];
    } else {
        x0 = __bfloat162float(Xh[base])        + __bfloat162float(Xl[base]);
        x1 = __bfloat162float(Xh[base + N_])   + __bfloat162float(Xl[base + N_]);
        x2 = __bfloat162float(Xh[base + 2*N_]) + __bfloat162float(Xl[base + 2*N_]);
    }
    float d0 = Dsrc[base], d1 = Dsrc[base + N_], d2 = Dsrc[base + 2*N_];
    float o0 = x0, o1 = x1, o2 = x2;
    float dot = x0*d0 + x1*d1 + x2*d2;
    if (dot < 0.f) {
        float dd = d0*d0 + d1*d1 + d2*d2;
        float s = dot / (dd + EPSF);
        o0 = x0 - s*d0; o1 = x1 - s*d1; o2 = x2 - s*d2;
    }
    bf16 h, l;
    split_bf(o0, h, l); Dh[base]        = h; Dl[base]        = l;
    split_bf(o1, h, l); Dh[base + N_]   = h; Dl[base + N_]   = l;
    split_bf(o2, h, l); Dh[base + 2*N_] = h; Dl[base + 2*N_] = l;
}

// ---------------- 7. head ----------------
__global__ void final_kernel(const float* __restrict__ Wd, const float* __restrict__ Wc,
                             float* __restrict__ out) {
    __shared__ float s_net[H3*24];
    __shared__ float s_act[H3*24];
    int o = threadIdx.x;
    for (int t = o; t < H3*24; t += 128) s_net[t] = g_P[t];
    __syncthreads();

    float dcol[24];
#pragma unroll
    for (int col = 0; col < 24; col++) dcol[col] = 0.f;
    for (int i = 0; i < H3; i++) {
        float w = Wd[o*H3 + i];
#pragma unroll
        for (int col = 0; col < 24; col++) dcol[col] += w * s_net[i*24 + col];
    }
#pragma unroll
    for (int b = 0; b < 8; b++) {
        float x0 = s_net[o*24 + b*3], x1 = s_net[o*24 + b*3 + 1], x2 = s_net[o*24 + b*3 + 2];
        float d0 = dcol[b*3], d1 = dcol[b*3 + 1], d2 = dcol[b*3 + 2];
        float dot = x0*d0 + x1*d1 + x2*d2;
        float a0 = x0, a1 = x1, a2 = x2;
        if (dot < 0.f) {
            float dd = d0*d0 + d1*d1 + d2*d2;
            float s = dot / (dd + EPSF);
            a0 = x0 - s*d0; a1 = x1 - s*d1; a2 = x2 - s*d2;
        }
        s_act[o*24 + b*3] = a0; s_act[o*24 + b*3 + 1] = a1; s_act[o*24 + b*3 + 2] = a2;
    }
    __syncthreads();

    float oc[24];
#pragma unroll
    for (int col = 0; col < 24; col++) oc[col] = 0.f;
    for (int i = 0; i < H3; i++) {
        float w = Wc[o*H3 + i];
#pragma unroll
        for (int col = 0; col < 24; col++) oc[col] += w * s_act[i*24 + col];
    }
#pragma unroll
    for (int col = 0; col < 24; col++) {
        int b = col / 3, v = col % 3;
        out[b*384 + o*3 + v] = oc[col];
    }
}

// ---------------- host ----------------
static float* symaddrf(const void* sym) {
    void* p = nullptr; cudaGetSymbolAddress(&p, sym); return (float*)p;
}
static bf16* symaddrb(const void* sym) {
    void* p = nullptr; cudaGetSymbolAddress(&p, sym); return (bf16*)p;
}

extern "C" void kernel_launch(void* const* d_in, const int* in_sizes, int n_in,
                              void* d_out, int out_size) {
    const float* p      = (const float*)d_in[0];
    const float* Wpos   = (const float*)d_in[1];
    const float* Wd0s   = (const float*)d_in[2];
    const float* W0s    = (const float*)d_in[3];
    const float* Wd1s   = (const float*)d_in[4];
    const float* W1s    = (const float*)d_in[5];
    const float* Wss    = (const float*)d_in[6];
    const float* Wd_act = (const float*)d_in[7];
    const float* Wc     = (const float*)d_in[8];
    float* out = (float*)d_out;

    float* DS    = symaddrf(g_DS);
    float* S     = DS + (size_t)C2*M_;
    float* D1    = symaddrf(g_D1);
    float* Wcat  = symaddrf(g_Wcat);
    float* Badd  = symaddrf(g_Badd);
    float* P     = symaddrf(g_P);
    bf16 *X0h = symaddrb(g_X0h), *X0l = symaddrb(g_X0l);
    bf16 *DSh = symaddrb(g_DSh), *DSl = symaddrb(g_DSl);
    bf16 *Nth = symaddrb(g_Nth), *Ntl = symaddrb(g_Ntl);
    bf16 *D1h = symaddrb(g_D1h), *D1l = symaddrb(g_D1l);
    bf16 *WcH = symaddrb(g_WcatH), *WcL = symaddrb(g_WcatL);
    bf16 *W0H = symaddrb(g_W0H),   *W0L = symaddrb(g_W0L);
    bf16 *Wd1H = symaddrb(g_Wd1H), *Wd1L = symaddrb(g_Wd1L);
    bf16 *W1H = symaddrb(g_W1H),   *W1L = symaddrb(g_W1L);

    knn_center_kernel<<<B_*4, 256>>>(p);                     // launch 1
    featpos_kernel<<<B_*3*8, 256>>>(Wpos);                   // launch 2
    wprep_kernel<<<3200, 256>>>(Wd0s, Wss, W0s, Wd1s, W1s);  // launch 3

    for (int i = 0; i < 5; i++) {
        size_t oc2 = (size_t)i*384*C2;
        const bf16* WciH = WcH + oc2; const bf16* WciL = WcL + oc2;
        const bf16* W0iH = W0H + (size_t)i*H3*C2;   const bf16* W0iL = W0L + (size_t)i*H3*C2;
        const bf16* Wd1iH = Wd1H + (size_t)i*H3*H3; const bf16* Wd1iL = Wd1L + (size_t)i*H3*H3;
        const bf16* W1iH = W1H + (size_t)i*H3*H3;   const bf16* W1iL = W1L + (size_t)i*H3*H3;

        if (i == 0) {
            // D;S = [Wd0;Ws] @ X0  (K=256)            -- launch 4: ncu target
            gemm_bfx3_kernel<<<dim3(192, 3), 256>>>(WciH, WciL, C2, X0h, X0l,
                DS, nullptr, nullptr, C2, nullptr, nullptr, nullptr);
        } else {
            badd_kernel<<<36, 256>>>(Wcat + oc2);
            gemm_bfx3_kernel<<<dim3(192, 3), 256>>>(WciH, WciL, C2, X0h, X0l,
                DS, nullptr, nullptr, H3, Badd, nullptr, nullptr);
        }
        // D' = lrelu(X, D) -> pairs
        lrelu_kernel<<<(C2*8192)/256, 256>>>(X0h, X0l, (i == 0) ? nullptr : P, DS,
                                             DSh, DSl, nullptr);
        // Nt = W0 @ D'  (K=256) -> pairs
        gemm_bfx3_kernel<<<dim3(192, 1), 256>>>(W0iH, W0iL, C2, DSh, DSl,
            nullptr, Nth, Ntl, C2, nullptr, nullptr, nullptr);
        // D1 = Wd1 @ Nt (K=128) -> fp32
        gemm_bfx3_kernel<<<dim3(192, 1), 256>>>(Wd1iH, Wd1iL, H3, Nth, Ntl,
            D1, nullptr, nullptr, H3, nullptr, nullptr, nullptr);
        // D1' = lrelu(Nt, D1) -> pairs; zeroes P for the fused pool below
        lrelu_kernel<<<(H3*8192)/256, 256>>>(Nth, Ntl, nullptr, D1, D1h, D1l, P);
        // netX = W1 @ D1' + S (K=128) -> pairs into X0; fused pool accumulates P
        gemm_bfx3_kernel<<<dim3(192, 1), 256>>>(W1iH, W1iL, H3, D1h, D1l,
            nullptr, X0h, X0l, H3, nullptr, S, P);
    }

    final_kernel<<<1, 128>>>(Wd_act, Wc, out);
}

// round 13
// speedup vs baseline: 1.0555x; 1.0215x over previous
#include <cuda_runtime.h>
#include <cuda_bf16.h>
#include <cstdint>

#define B_   8
#define N_   1024
#define M_   24576      // B_*3*N_
#define C2   256
#define H3   128
#define KNN_ 20
#define EPSF 1e-6f

typedef __nv_bfloat16 bf16;

// ---------------- scratch (allocation-free: __device__ globals) ----------------
__device__ float g_pc[B_*N_*3];
__device__ float g_m [B_*N_*3];
__device__ bf16  g_X0h[C2*M_], g_X0l[C2*M_];     // pos feats / netX, bf16 hi/lo planes
__device__ float g_DS[384*M_];                   // gemm1 out fp32: rows 0..255 = D, 256..383 = S
__device__ bf16  g_DSh[C2*M_], g_DSl[C2*M_];     // lrelu1 out pairs
__device__ bf16  g_Nth[H3*M_], g_Ntl[H3*M_];
__device__ float g_D1[H3*M_];
__device__ bf16  g_D1h[H3*M_], g_D1l[H3*M_];
__device__ float g_P [H3*24];
__device__ float g_Wcat[5*384*C2];
__device__ float g_Badd[384*24];
__device__ bf16  g_WcatH[5*384*C2], g_WcatL[5*384*C2];
__device__ bf16  g_W0H[5*H3*C2],    g_W0L[5*H3*C2];
__device__ bf16  g_Wd1H[5*H3*H3],   g_Wd1L[5*H3*H3];
__device__ bf16  g_W1H[5*H3*H3],    g_W1L[5*H3*H3];

// ---------------- helpers ----------------
__device__ __forceinline__ void split_bf(float x, bf16& h, bf16& l) {
    h = __float2bfloat16_rn(x);
    l = __float2bfloat16_rn(x - __bfloat162float(h));
}
__device__ __forceinline__ void cp16g(void* smem, const void* g) {
    uint32_t s = (uint32_t)__cvta_generic_to_shared(smem);
    asm volatile("cp.async.cg.shared.global [%0], [%1], 16;" :: "r"(s), "l"(g));
}
__device__ __forceinline__ uint32_t scvt(const void* p) {
    return (uint32_t)__cvta_generic_to_shared(p);
}
__device__ __forceinline__ void ldsm4(uint32_t* r, uint32_t a) {
    asm volatile("ldmatrix.sync.aligned.m8n8.x4.shared.b16 {%0,%1,%2,%3}, [%4];"
        : "=r"(r[0]), "=r"(r[1]), "=r"(r[2]), "=r"(r[3]) : "r"(a));
}
__device__ __forceinline__ void ldsm4t(uint32_t* r, uint32_t a) {
    asm volatile("ldmatrix.sync.aligned.m8n8.x4.trans.shared.b16 {%0,%1,%2,%3}, [%4];"
        : "=r"(r[0]), "=r"(r[1]), "=r"(r[2]), "=r"(r[3]) : "r"(a));
}
__device__ __forceinline__ void mma16(float* c, const uint32_t* a, const uint32_t* b) {
    asm volatile("mma.sync.aligned.m16n8k16.row.col.f32.bf16.bf16.f32 "
        "{%0,%1,%2,%3}, {%4,%5,%6,%7}, {%8,%9}, {%0,%1,%2,%3};"
        : "+f"(c[0]), "+f"(c[1]), "+f"(c[2]), "+f"(c[3])
        : "r"(a[0]), "r"(a[1]), "r"(a[2]), "r"(a[3]), "r"(b[0]), "r"(b[1]));
}

// ---------------- 1. fused center + KNN -> mean of neighbor coords ----------------
__global__ void knn_center_kernel(const float* __restrict__ p) {
    int b     = blockIdx.x >> 2;
    int chunk = blockIdx.x & 3;
    __shared__ float sp[N_*3];
    __shared__ float sxx[N_];
    __shared__ float red[3][256];
    int tid = threadIdx.x;
    for (int t = tid; t < N_*3; t += 256) sp[t] = p[b*N_*3 + t];
    __syncthreads();
    float s0 = 0.f, s1 = 0.f, s2 = 0.f;
    for (int n = tid; n < N_; n += 256) {
        s0 += sp[n*3]; s1 += sp[n*3+1]; s2 += sp[n*3+2];
    }
    red[0][tid] = s0; red[1][tid] = s1; red[2][tid] = s2;
    __syncthreads();
    for (int st = 128; st > 0; st >>= 1) {
        if (tid < st) {
            red[0][tid] += red[0][tid + st];
            red[1][tid] += red[1][tid + st];
            red[2][tid] += red[2][tid + st];
        }
        __syncthreads();
    }
    float m0 = red[0][0] / N_, m1 = red[1][0] / N_, m2 = red[2][0] / N_;
    for (int n = tid; n < N_; n += 256) {
        float x = sp[n*3] - m0, y = sp[n*3+1] - m1, z = sp[n*3+2] - m2;
        sp[n*3] = x; sp[n*3+1] = y; sp[n*3+2] = z;
        if (chunk == 0) {
            float* o = g_pc + (size_t)(b*N_ + n)*3;
            o[0] = x; o[1] = y; o[2] = z;
        }
    }
    __syncthreads();
    for (int t = tid; t < N_; t += 256) {
        float x = sp[t*3], y = sp[t*3+1], z = sp[t*3+2];
        sxx[t] = x*x + y*y + z*z;
    }
    __syncthreads();

    int i = chunk*256 + tid;
    float xi = sp[i*3], yi = sp[i*3+1], zi = sp[i*3+2];
    float xxi = sxx[i];

    float bd[KNN_]; int bi[KNN_];
#pragma unroll
    for (int t = 0; t < KNN_; t++) { bd[t] = -3.4e38f; bi[t] = 0; }

    for (int j = 0; j < N_; j++) {
        float dot = xi*sp[j*3] + yi*sp[j*3+1] + zi*sp[j*3+2];
        float nd  = 2.f*dot - xxi - sxx[j];
        if (nd > bd[KNN_-1]) {                      // strict > => ties keep lower index
            int t = KNN_-1;
            while (t > 0 && bd[t-1] < nd) { bd[t] = bd[t-1]; bi[t] = bi[t-1]; t--; }
            bd[t] = nd; bi[t] = j;
        }
    }
    float a0 = 0.f, a1 = 0.f, a2 = 0.f;
#pragma unroll
    for (int t = 0; t < KNN_; t++) {
        int j = bi[t];
        a0 += sp[j*3]; a1 += sp[j*3+1]; a2 += sp[j*3+2];
    }
    float* o = g_m + (size_t)(b*N_ + i)*3;
    o[0] = a0 / KNN_; o[1] = a1 / KNN_; o[2] = a2 / KNN_;
}

// ---------------- 2. fused edge-feature + W_pos + pool_k -> X0 hi/lo ----------------
__global__ void featpos_kernel(const float* __restrict__ Wpos) {
    int bk = blockIdx.x;                 // b(8) * v(3) * chunk(8)
    int b = bk / 24; int rem = bk % 24;
    int v = rem / 8; int chunk = rem % 8;
    int n0 = chunk * 128;
    __shared__ float f0[128], f1[128], f2[128];
    if (threadIdx.x < 128) {
        int n = n0 + threadIdx.x;
        const float* pp = g_pc + (size_t)(b*N_ + n)*3;
        const float* mm = g_m  + (size_t)(b*N_ + n)*3;
        float p0 = pp[0], p1 = pp[1], p2 = pp[2];
        float m0 = mm[0], m1 = mm[1], m2 = mm[2];
        float pv = (v == 0) ? p0 : ((v == 1) ? p1 : p2);
        float mv = (v == 0) ? m0 : ((v == 1) ? m1 : m2);
        float cv;
        if (v == 0)      cv = m1*p2 - m2*p1;
        else if (v == 1) cv = m2*p0 - m0*p2;
        else             cv = m0*p1 - m1*p0;
        f0[threadIdx.x] = mv - pv;
        f1[threadIdx.x] = pv;
        f2[threadIdx.x] = cv;
    }
    __syncthreads();
    int nl = threadIdx.x & 127;
    int oo = threadIdx.x >> 7;
    size_t colbase = (size_t)(b*3 + v)*N_ + n0;
    for (int ob = 0; ob < C2; ob += 2) {
        int o = ob + oo;
        float w0 = Wpos[o*3], w1 = Wpos[o*3+1], w2 = Wpos[o*3+2];
        float val = w0*f0[nl] + w1*f1[nl] + w2*f2[nl];
        size_t idx = (size_t)o*M_ + colbase + nl;
        bf16 h, l; split_bf(val, h, l);
        g_X0h[idx] = h; g_X0l[idx] = l;
    }
}

// ---------------- 3. ALL weight prep in one launch ----------------
__global__ void wprep_kernel(const float* __restrict__ Wd0s, const float* __restrict__ Wss,
                             const float* __restrict__ W0s, const float* __restrict__ Wd1s,
                             const float* __restrict__ W1s) {
    int idx = blockIdx.x * 256 + threadIdx.x;
    const int R0 = 5*384*C2;            // 491520
    const int R1 = R0 + 5*H3*C2;        // 655360
    const int R2 = R1 + 5*H3*H3;        // 737280
    bf16 h, l;
    if (idx < R0) {
        int i   = idx / (384*C2);
        int rem = idx % (384*C2);
        int r = rem / C2, c = rem % C2;
        float v = (r < C2) ? Wd0s[(size_t)i*C2*C2 + r*C2 + c]
                           : Wss [(size_t)i*H3*C2 + (r - C2)*C2 + c];
        g_Wcat[idx] = v;
        split_bf(v, h, l);
        g_WcatH[idx] = h; g_WcatL[idx] = l;
    } else if (idx < R1) {
        int j = idx - R0;
        split_bf(W0s[j], h, l);  g_W0H[j] = h;  g_W0L[j] = l;
    } else if (idx < R2) {
        int j = idx - R1;
        split_bf(Wd1s[j], h, l); g_Wd1H[j] = h; g_Wd1L[j] = l;
    } else {
        int j = idx - R2;
        split_bf(W1s[j], h, l);  g_W1H[j] = h;  g_W1L[j] = l;
    }
}

// ---------------- 3d. Badd[384][24] = Wcat[:,128:] @ P ----------------
__global__ void badd_kernel(const float* __restrict__ Wcat) {
    int idx = blockIdx.x * 256 + threadIdx.x;   // 9216
    if (idx >= 384*24) return;
    int r = idx / 24, cg = idx % 24;
    float s = 0.f;
#pragma unroll 8
    for (int k = 0; k < H3; k++)
        s += Wcat[r*C2 + H3 + k] * g_P[k*24 + cg];
    g_Badd[idx] = s;
}

// ---------------- 4. bf16x3 tensor-core GEMM, 128x128 tile (unchanged from R12) -------
__global__ __launch_bounds__(256, 2)
void gemm_bfx3_kernel(const bf16* __restrict__ Ah, const bf16* __restrict__ Al, int lda,
                      const bf16* __restrict__ Bh, const bf16* __restrict__ Bl,
                      float* __restrict__ Yf, bf16* __restrict__ Yh, bf16* __restrict__ Yl,
                      int K, const float* __restrict__ Badd, const float* __restrict__ Add,
                      float* __restrict__ Psum)
{
    const int SA = 16, SB = 136;
    __shared__ bf16 sAh[2][128*SA], sAl[2][128*SA];
    __shared__ bf16 sBh[2][16*SB],  sBl[2][16*SB];
    int tid = threadIdx.x, lane = tid & 31, wid = tid >> 5;
    int warp_m = wid >> 2, warp_n = wid & 3;
    int gid = lane >> 2, tig = lane & 3;
    int nBase = blockIdx.x * 128, oBase = blockIdx.y * 128;

    int aRow = tid >> 1, aG = tid & 1;
    const bf16* Agh = Ah + (size_t)(oBase + aRow)*lda + aG*8;
    const bf16* Agl = Al + (size_t)(oBase + aRow)*lda + aG*8;
    int aOffSm = aRow*SA + ((aG ^ ((aRow >> 2) & 1)) << 3);

    const bool bHi = (tid < 128);
    int bs   = tid & 127;
    int bRow = bs >> 4, bC = (bs & 15) * 8;
    const bf16* Bg = (bHi ? Bh : Bl) + (size_t)bRow*M_ + nBase + bC;
    int bOff0 = bRow*SB + bC;
    int bOff1 = (bRow + 8)*SB + bC;

    int selA = ((lane >> 3) & 1) * 8 + (lane & 7);
    int halfA = lane >> 4;
    uint32_t aOff[4];
#pragma unroll
    for (int mt = 0; mt < 4; mt++) {
        int row = warp_m*64 + mt*16 + selA;
        aOff[mt] = (uint32_t)((row*SA + ((halfA ^ ((row >> 2) & 1)) << 3)) * 2);
    }
    int selBk = ((lane >> 3) & 1) * 8 + (lane & 7);
    int selBn = (lane >> 4) * 8;
    uint32_t bOff[2];
#pragma unroll
    for (int j = 0; j < 2; j++)
        bOff[j] = (uint32_t)((selBk*SB + warp_n*32 + j*16 + selBn) * 2);

    uint32_t sAhB[2] = { scvt(sAh[0]), scvt(sAh[1]) };
    uint32_t sAlB[2] = { scvt(sAl[0]), scvt(sAl[1]) };
    uint32_t sBhB[2] = { scvt(sBh[0]), scvt(sBh[1]) };
    uint32_t sBlB[2] = { scvt(sBl[0]), scvt(sBl[1]) };

    int stages = K >> 4;
    float c[4][4][4];
#pragma unroll
    for (int mt = 0; mt < 4; mt++)
#pragma unroll
        for (int nt = 0; nt < 4; nt++)
#pragma unroll
            for (int r = 0; r < 4; r++) c[mt][nt][r] = 0.f;

#define LOAD_STAGE(s, buf)                                              \
    do {                                                                \
        int k0_ = (s) * 16;                                             \
        cp16g(&sAh[buf][aOffSm], Agh + k0_);                            \
        cp16g(&sAl[buf][aOffSm], Agl + k0_);                            \
        bf16* bdst = bHi ? sBh[buf] : sBl[buf];                         \
        cp16g(bdst + bOff0, Bg + (size_t)k0_*M_);                       \
        cp16g(bdst + bOff1, Bg + (size_t)(k0_ + 8)*M_);                 \
        asm volatile("cp.async.commit_group;");                         \
    } while (0)

    LOAD_STAGE(0, 0);
    if (stages > 1) LOAD_STAGE(1, 1);

    for (int s = 0; s < stages; s++) {
        if (s == stages - 1) asm volatile("cp.async.wait_group 0;");
        else                 asm volatile("cp.async.wait_group 1;");
        __syncthreads();
        int buf = s & 1;

        uint32_t bh[2][4], bl[2][4];
        ldsm4t(bh[0], sBhB[buf] + bOff[0]);
        ldsm4t(bh[1], sBhB[buf] + bOff[1]);
        ldsm4t(bl[0], sBlB[buf] + bOff[0]);
        ldsm4t(bl[1], sBlB[buf] + bOff[1]);

#pragma unroll
        for (int h2 = 0; h2 < 2; h2++) {
            uint32_t ah[2][4], al[2][4];
            ldsm4(ah[0], sAhB[buf] + aOff[h2*2]);
            ldsm4(ah[1], sAhB[buf] + aOff[h2*2 + 1]);
            ldsm4(al[0], sAlB[buf] + aOff[h2*2]);
            ldsm4(al[1], sAlB[buf] + aOff[h2*2 + 1]);
#pragma unroll
            for (int m2 = 0; m2 < 2; m2++)
#pragma unroll
                for (int nt = 0; nt < 4; nt++) {
                    const uint32_t* bhf = &bh[nt >> 1][(nt & 1)*2];
                    const uint32_t* blf = &bl[nt >> 1][(nt & 1)*2];
                    float* cc = c[h2*2 + m2][nt];
                    mma16(cc, ah[m2], bhf);   // hi*hi
                    mma16(cc, ah[m2], blf);   // hi*lo
                    mma16(cc, al[m2], bhf);   // lo*hi
                }
        }
        __syncthreads();
        if (s + 2 < stages) LOAD_STAGE(s + 2, buf);
    }
#undef LOAD_STAGE

    int cg = nBase >> 10;
    float ps0[4] = {0.f, 0.f, 0.f, 0.f}, ps1[4] = {0.f, 0.f, 0.f, 0.f};
#pragma unroll
    for (int mt = 0; mt < 4; mt++) {
#pragma unroll
        for (int nt = 0; nt < 4; nt++) {
            int r0 = oBase + warp_m*64 + mt*16 + gid;
            int r1 = r0 + 8;
            int col = nBase + warp_n*32 + nt*8 + tig*2;
            float* cc = c[mt][nt];
            float ba0 = 0.f, ba1 = 0.f;
            if (Badd) { ba0 = Badd[r0*24 + cg]; ba1 = Badd[r1*24 + cg]; }
            size_t p0 = (size_t)r0*M_ + col;
            size_t p1 = (size_t)r1*M_ + col;
            float o0 = cc[0] + ba0, o1 = cc[1] + ba0;
            float o2 = cc[2] + ba1, o3 = cc[3] + ba1;
            if (Add) {
                float2 t0 = *(const float2*)&Add[p0];
                float2 t1 = *(const float2*)&Add[p1];
                o0 += t0.x; o1 += t0.y; o2 += t1.x; o3 += t1.y;
            }
            ps0[mt] += o0 + o1;
            ps1[mt] += o2 + o3;
            if (Yf) {
                *(float2*)&Yf[p0] = make_float2(o0, o1);
                *(float2*)&Yf[p1] = make_float2(o2, o3);
            } else {
                __nv_bfloat162 h0, l0, h1, l1;
                split_bf(o0, h0.x, l0.x); split_bf(o1, h0.y, l0.y);
                split_bf(o2, h1.x, l1.x); split_bf(o3, h1.y, l1.y);
                *(__nv_bfloat162*)&Yh[p0] = h0;
                *(__nv_bfloat162*)&Yl[p0] = l0;
                *(__nv_bfloat162*)&Yh[p1] = h1;
                *(__nv_bfloat162*)&Yl[p1] = l1;
            }
        }
    }
    if (Psum) {
        const float invN = 1.f / N_;
#pragma unroll
        for (int mt = 0; mt < 4; mt++) {
            float a = ps0[mt], b2 = ps1[mt];
            a  += __shfl_xor_sync(0xffffffffu, a, 1);
            a  += __shfl_xor_sync(0xffffffffu, a, 2);
            b2 += __shfl_xor_sync(0xffffffffu, b2, 1);
            b2 += __shfl_xor_sync(0xffffffffu, b2, 2);
            if (tig == 0) {
                int r0 = oBase + warp_m*64 + mt*16 + gid;
                atomicAdd(&Psum[r0*24 + cg], a * invN);
                atomicAdd(&Psum[(r0 + 8)*24 + cg], b2 * invN);
            }
        }
    }
}

// ---------------- 5. VN leaky-relu, 8-wide vectorized ----------------
// Each thread: 8 consecutive points, all 3 vector comps. 16B loads/stores.
// idx layout: c = idx>>10, b = (idx>>7)&7, n8 = idx&127.
__global__ void lrelu_kernel(const bf16* __restrict__ Xh, const bf16* __restrict__ Xl,
                             const float* __restrict__ P, const float* __restrict__ Dsrc,
                             bf16* __restrict__ Dh, bf16* __restrict__ Dl,
                             float* __restrict__ Pzero) {
    int idx = blockIdx.x * 256 + threadIdx.x;
    if (Pzero && idx < H3*24) Pzero[idx] = 0.f;
    int n = (idx & 127) * 8;
    int b = (idx >> 7) & 7;
    int c = idx >> 10;
    size_t base = (size_t)c*M_ + (size_t)b*3*N_ + n;

    float x[3][8], d[3][8];
#pragma unroll
    for (int v = 0; v < 3; v++) {
        size_t o = base + (size_t)v*N_;
        if (P != nullptr && c >= H3) {
            float xv = P[(c - H3)*24 + b*3 + v];
#pragma unroll
            for (int j = 0; j < 8; j++) x[v][j] = xv;
        } else {
            union { uint4 u; __nv_bfloat162 b2[4]; } Hd, Ld;
            Hd.u = *(const uint4*)&Xh[o];
            Ld.u = *(const uint4*)&Xl[o];
#pragma unroll
            for (int j = 0; j < 4; j++) {
                x[v][2*j]   = __bfloat162float(Hd.b2[j].x) + __bfloat162float(Ld.b2[j].x);
                x[v][2*j+1] = __bfloat162float(Hd.b2[j].y) + __bfloat162float(Ld.b2[j].y);
            }
        }
        float4 d0 = *(const float4*)&Dsrc[o];
        float4 d1 = *(const float4*)&Dsrc[o + 4];
        d[v][0] = d0.x; d[v][1] = d0.y; d[v][2] = d0.z; d[v][3] = d0.w;
        d[v][4] = d1.x; d[v][5] = d1.y; d[v][6] = d1.z; d[v][7] = d1.w;
    }
#pragma unroll
    for (int j = 0; j < 8; j++) {
        float dot = x[0][j]*d[0][j] + x[1][j]*d[1][j] + x[2][j]*d[2][j];
        if (dot < 0.f) {
            float dd = d[0][j]*d[0][j] + d[1][j]*d[1][j] + d[2][j]*d[2][j];
            float s = dot / (dd + EPSF);
            x[0][j] -= s*d[0][j]; x[1][j] -= s*d[1][j]; x[2][j] -= s*d[2][j];
        }
    }
#pragma unroll
    for (int v = 0; v < 3; v++) {
        size_t o = base + (size_t)v*N_;
        union { uint4 u; __nv_bfloat162 b2[4]; } Ho, Lo;
#pragma unroll
        for (int j = 0; j < 4; j++) {
            split_bf(x[v][2*j],   Ho.b2[j].x, Lo.b2[j].x);
            split_bf(x[v][2*j+1], Ho.b2[j].y, Lo.b2[j].y);
        }
        *(uint4*)&Dh[o] = Ho.u;
        *(uint4*)&Dl[o] = Lo.u;
    }
}

// ---------------- 7. head ----------------
__global__ void final_kernel(const float* __restrict__ Wd, const float* __restrict__ Wc,
                             float* __restrict__ out) {
    __shared__ float s_net[H3*24];
    __shared__ float s_act[H3*24];
    int o = threadIdx.x;
    for (int t = o; t < H3*24; t += 128) s_net[t] = g_P[t];
    __syncthreads();

    float dcol[24];
#pragma unroll
    for (int col = 0; col < 24; col++) dcol[col] = 0.f;
    for (int i = 0; i < H3; i++) {
        float w = Wd[o*H3 + i];
#pragma unroll
        for (int col = 0; col < 24; col++) dcol[col] += w * s_net[i*24 + col];
    }
#pragma unroll
    for (int b = 0; b < 8; b++) {
        float x0 = s_net[o*24 + b*3], x1 = s_net[o*24 + b*3 + 1], x2 = s_net[o*24 + b*3 + 2];
        float d0 = dcol[b*3], d1 = dcol[b*3 + 1], d2 = dcol[b*3 + 2];
        float dot = x0*d0 + x1*d1 + x2*d2;
        float a0 = x0, a1 = x1, a2 = x2;
        if (dot < 0.f) {
            float dd = d0*d0 + d1*d1 + d2*d2;
            float s = dot / (dd + EPSF);
            a0 = x0 - s*d0; a1 = x1 - s*d1; a2 = x2 - s*d2;
        }
        s_act[o*24 + b*3] = a0; s_act[o*24 + b*3 + 1] = a1; s_act[o*24 + b*3 + 2] = a2;
    }
    __syncthreads();

    float oc[24];
#pragma unroll
    for (int col = 0; col < 24; col++) oc[col] = 0.f;
    for (int i = 0; i < H3; i++) {
        float w = Wc[o*H3 + i];
#pragma unroll
        for (int col = 0; col < 24; col++) oc[col] += w * s_act[i*24 + col];
    }
#pragma unroll
    for (int col = 0; col < 24; col++) {
        int b = col / 3, v = col % 3;
        out[b*384 + o*3 + v] = oc[col];
    }
}

// ---------------- host ----------------
static float* symaddrf(const void* sym) {
    void* p = nullptr; cudaGetSymbolAddress(&p, sym); return (float*)p;
}
static bf16* symaddrb(const void* sym) {
    void* p = nullptr; cudaGetSymbolAddress(&p, sym); return (bf16*)p;
}

extern "C" void kernel_launch(void* const* d_in, const int* in_sizes, int n_in,
                              void* d_out, int out_size) {
    const float* p      = (const float*)d_in[0];
    const float* Wpos   = (const float*)d_in[1];
    const float* Wd0s   = (const float*)d_in[2];
    const float* W0s    = (const float*)d_in[3];
    const float* Wd1s   = (const float*)d_in[4];
    const float* W1s    = (const float*)d_in[5];
    const float* Wss    = (const float*)d_in[6];
    const float* Wd_act = (const float*)d_in[7];
    const float* Wc     = (const float*)d_in[8];
    float* out = (float*)d_out;

    float* DS    = symaddrf(g_DS);
    float* S     = DS + (size_t)C2*M_;
    float* D1    = symaddrf(g_D1);
    float* Wcat  = symaddrf(g_Wcat);
    float* Badd  = symaddrf(g_Badd);
    float* P     = symaddrf(g_P);
    bf16 *X0h = symaddrb(g_X0h), *X0l = symaddrb(g_X0l);
    bf16 *DSh = symaddrb(g_DSh), *DSl = symaddrb(g_DSl);
    bf16 *Nth = symaddrb(g_Nth), *Ntl = symaddrb(g_Ntl);
    bf16 *D1h = symaddrb(g_D1h), *D1l = symaddrb(g_D1l);
    bf16 *WcH = symaddrb(g_WcatH), *WcL = symaddrb(g_WcatL);
    bf16 *W0H = symaddrb(g_W0H),   *W0L = symaddrb(g_W0L);
    bf16 *Wd1H = symaddrb(g_Wd1H), *Wd1L = symaddrb(g_Wd1L);
    bf16 *W1H = symaddrb(g_W1H),   *W1L = symaddrb(g_W1L);

    knn_center_kernel<<<B_*4, 256>>>(p);                     // launch 1
    featpos_kernel<<<B_*3*8, 256>>>(Wpos);                   // launch 2
    wprep_kernel<<<3200, 256>>>(Wd0s, Wss, W0s, Wd1s, W1s);  // launch 3

    for (int i = 0; i < 5; i++) {
        size_t oc2 = (size_t)i*384*C2;
        const bf16* WciH = WcH + oc2; const bf16* WciL = WcL + oc2;
        const bf16* W0iH = W0H + (size_t)i*H3*C2;   const bf16* W0iL = W0L + (size_t)i*H3*C2;
        const bf16* Wd1iH = Wd1H + (size_t)i*H3*H3; const bf16* Wd1iL = Wd1L + (size_t)i*H3*H3;
        const bf16* W1iH = W1H + (size_t)i*H3*H3;   const bf16* W1iL = W1L + (size_t)i*H3*H3;

        if (i == 0) {
            // D;S = [Wd0;Ws] @ X0  (K=256)            -- launch 4: ncu target
            gemm_bfx3_kernel<<<dim3(192, 3), 256>>>(WciH, WciL, C2, X0h, X0l,
                DS, nullptr, nullptr, C2, nullptr, nullptr, nullptr);
        } else {
            badd_kernel<<<36, 256>>>(Wcat + oc2);
            gemm_bfx3_kernel<<<dim3(192, 3), 256>>>(WciH, WciL, C2, X0h, X0l,
                DS, nullptr, nullptr, H3, Badd, nullptr, nullptr);
        }
        // D' = lrelu(X, D) -> pairs  (8-wide: 256ch * 8 b * 128 n8 / 256 = 1024 blocks)
        lrelu_kernel<<<1024, 256>>>(X0h, X0l, (i == 0) ? nullptr : P, DS,
                                    DSh, DSl, nullptr);
        // Nt = W0 @ D'  (K=256) -> pairs
        gemm_bfx3_kernel<<<dim3(192, 1), 256>>>(W0iH, W0iL, C2, DSh, DSl,
            nullptr, Nth, Ntl, C2, nullptr, nullptr, nullptr);
        // D1 = Wd1 @ Nt (K=128) -> fp32
        gemm_bfx3_kernel<<<dim3(192, 1), 256>>>(Wd1iH, Wd1iL, H3, Nth, Ntl,
            D1, nullptr, nullptr, H3, nullptr, nullptr, nullptr);
        // D1' = lrelu(Nt, D1) -> pairs (512 blocks); zeroes P for the fused pool below
        lrelu_kernel<<<512, 256>>>(Nth, Ntl, nullptr, D1, D1h, D1l, P);
        // netX = W1 @ D1' + S (K=128) -> pairs into X0; fused pool accumulates P
        gemm_bfx3_kernel<<<dim3(192, 1), 256>>>(W1iH, W1iL, H3, D1h, D1l,
            nullptr, X0h, X0l, H3, nullptr, S, P);
    }

    final_kernel<<<1, 128>>>(Wd_act, Wc, out);
}

// round 14
// speedup vs baseline: 1.0586x; 1.0029x over previous
#include <cuda_runtime.h>
#include <cuda_bf16.h>
#include <cstdint>

#define B_   8
#define N_   1024
#define M_   24576      // B_*3*N_
#define C2   256
#define H3   128
#define KNN_ 20
#define EPSF 1e-6f

typedef __nv_bfloat16 bf16;

// ---------------- scratch (allocation-free: __device__ globals) ----------------
__device__ float g_pc[B_*N_*3];
__device__ float g_m [B_*N_*3];
__device__ bf16  g_X0h[C2*M_], g_X0l[C2*M_];     // pos feats / netX, bf16 hi/lo planes
__device__ float g_DS[384*M_];                   // gemm1 out fp32: rows 0..255 = D, 256..383 = S
__device__ bf16  g_DSh[C2*M_], g_DSl[C2*M_];     // lrelu1 out pairs
__device__ bf16  g_Nth[H3*M_], g_Ntl[H3*M_];
__device__ float g_D1[H3*M_];
__device__ bf16  g_D1h[H3*M_], g_D1l[H3*M_];
__device__ float g_P [H3*24];
__device__ float g_Wcat[5*384*C2];
__device__ float g_Badd[384*24];
__device__ bf16  g_WcatH[5*384*C2], g_WcatL[5*384*C2];
__device__ bf16  g_W0H[5*H3*C2],    g_W0L[5*H3*C2];
__device__ bf16  g_Wd1H[5*H3*H3],   g_Wd1L[5*H3*H3];
__device__ bf16  g_W1H[5*H3*H3],    g_W1L[5*H3*H3];

// ---------------- helpers ----------------
__device__ __forceinline__ void split_bf(float x, bf16& h, bf16& l) {
    h = __float2bfloat16_rn(x);
    l = __float2bfloat16_rn(x - __bfloat162float(h));
}
__device__ __forceinline__ void cp16g(void* smem, const void* g) {
    uint32_t s = (uint32_t)__cvta_generic_to_shared(smem);
    asm volatile("cp.async.cg.shared.global [%0], [%1], 16;" :: "r"(s), "l"(g));
}
__device__ __forceinline__ uint32_t scvt(const void* p) {
    return (uint32_t)__cvta_generic_to_shared(p);
}
__device__ __forceinline__ void ldsm4(uint32_t* r, uint32_t a) {
    asm volatile("ldmatrix.sync.aligned.m8n8.x4.shared.b16 {%0,%1,%2,%3}, [%4];"
        : "=r"(r[0]), "=r"(r[1]), "=r"(r[2]), "=r"(r[3]) : "r"(a));
}
__device__ __forceinline__ void ldsm4t(uint32_t* r, uint32_t a) {
    asm volatile("ldmatrix.sync.aligned.m8n8.x4.trans.shared.b16 {%0,%1,%2,%3}, [%4];"
        : "=r"(r[0]), "=r"(r[1]), "=r"(r[2]), "=r"(r[3]) : "r"(a));
}
__device__ __forceinline__ void mma16(float* c, const uint32_t* a, const uint32_t* b) {
    asm volatile("mma.sync.aligned.m16n8k16.row.col.f32.bf16.bf16.f32 "
        "{%0,%1,%2,%3}, {%4,%5,%6,%7}, {%8,%9}, {%0,%1,%2,%3};"
        : "+f"(c[0]), "+f"(c[1]), "+f"(c[2]), "+f"(c[3])
        : "r"(a[0]), "r"(a[1]), "r"(a[2]), "r"(a[3]), "r"(b[0]), "r"(b[1]));
}

// ---------------- 1. fused center + KNN -> mean of neighbor coords ----------------
__global__ void knn_center_kernel(const float* __restrict__ p) {
    int b     = blockIdx.x >> 2;
    int chunk = blockIdx.x & 3;
    __shared__ float sp[N_*3];
    __shared__ float sxx[N_];
    __shared__ float red[3][256];
    int tid = threadIdx.x;
    for (int t = tid; t < N_*3; t += 256) sp[t] = p[b*N_*3 + t];
    __syncthreads();
    float s0 = 0.f, s1 = 0.f, s2 = 0.f;
    for (int n = tid; n < N_; n += 256) {
        s0 += sp[n*3]; s1 += sp[n*3+1]; s2 += sp[n*3+2];
    }
    red[0][tid] = s0; red[1][tid] = s1; red[2][tid] = s2;
    __syncthreads();
    for (int st = 128; st > 0; st >>= 1) {
        if (tid < st) {
            red[0][tid] += red[0][tid + st];
            red[1][tid] += red[1][tid + st];
            red[2][tid] += red[2][tid + st];
        }
        __syncthreads();
    }
    float m0 = red[0][0] / N_, m1 = red[1][0] / N_, m2 = red[2][0] / N_;
    for (int n = tid; n < N_; n += 256) {
        float x = sp[n*3] - m0, y = sp[n*3+1] - m1, z = sp[n*3+2] - m2;
        sp[n*3] = x; sp[n*3+1] = y; sp[n*3+2] = z;
        if (chunk == 0) {
            float* o = g_pc + (size_t)(b*N_ + n)*3;
            o[0] = x; o[1] = y; o[2] = z;
        }
    }
    __syncthreads();
    for (int t = tid; t < N_; t += 256) {
        float x = sp[t*3], y = sp[t*3+1], z = sp[t*3+2];
        sxx[t] = x*x + y*y + z*z;
    }
    __syncthreads();

    int i = chunk*256 + tid;
    float xi = sp[i*3], yi = sp[i*3+1], zi = sp[i*3+2];
    float xxi = sxx[i];

    float bd[KNN_]; int bi[KNN_];
#pragma unroll
    for (int t = 0; t < KNN_; t++) { bd[t] = -3.4e38f; bi[t] = 0; }

    for (int j = 0; j < N_; j++) {
        float dot = xi*sp[j*3] + yi*sp[j*3+1] + zi*sp[j*3+2];
        float nd  = 2.f*dot - xxi - sxx[j];
        if (nd > bd[KNN_-1]) {                      // strict > => ties keep lower index
            int t = KNN_-1;
            while (t > 0 && bd[t-1] < nd) { bd[t] = bd[t-1]; bi[t] = bi[t-1]; t--; }
            bd[t] = nd; bi[t] = j;
        }
    }
    float a0 = 0.f, a1 = 0.f, a2 = 0.f;
#pragma unroll
    for (int t = 0; t < KNN_; t++) {
        int j = bi[t];
        a0 += sp[j*3]; a1 += sp[j*3+1]; a2 += sp[j*3+2];
    }
    float* o = g_m + (size_t)(b*N_ + i)*3;
    o[0] = a0 / KNN_; o[1] = a1 / KNN_; o[2] = a2 / KNN_;
}

// ---------------- 2. fused edge-feature + W_pos + pool_k -> X0 hi/lo (vectorized) -----
// Block: (b, v). Threads: 16 groups of 16; each pass covers 16 o-rows; thread handles
// one o and 8 consecutive n per inner step -> uint4 stores.
__global__ void featpos_kernel(const float* __restrict__ Wpos) {
    int bk = blockIdx.x;                 // 0..23 = b(8) * v(3)
    int b = bk / 3, v = bk % 3;
    __shared__ float f0[N_], f1[N_], f2[N_];
    int tid = threadIdx.x;
    for (int n = tid; n < N_; n += 256) {
        const float* pp = g_pc + (size_t)(b*N_ + n)*3;
        const float* mm = g_m  + (size_t)(b*N_ + n)*3;
        float p0 = pp[0], p1 = pp[1], p2 = pp[2];
        float m0 = mm[0], m1 = mm[1], m2 = mm[2];
        float pv = (v == 0) ? p0 : ((v == 1) ? p1 : p2);
        float mv = (v == 0) ? m0 : ((v == 1) ? m1 : m2);
        float cv;
        if (v == 0)      cv = m1*p2 - m2*p1;
        else if (v == 1) cv = m2*p0 - m0*p2;
        else             cv = m0*p1 - m1*p0;
        f0[n] = mv - pv;
        f1[n] = pv;
        f2[n] = cv;
    }
    __syncthreads();
    int og  = tid >> 4;                  // 0..15: o sub-index within pass
    int ng  = tid & 15;                  // 0..15: which 64-elem... (16 groups x 8 n) x 8 passes
    size_t colbase = (size_t)(b*3 + v)*N_;
    for (int op = 0; op < C2; op += 16) {
        int o = op + og;
        float w0 = Wpos[o*3], w1 = Wpos[o*3+1], w2 = Wpos[o*3+2];
        for (int np = 0; np < N_; np += 128) {
            int n = np + ng*8;
            union { uint4 u; __nv_bfloat162 b2[4]; } Ho, Lo;
#pragma unroll
            for (int j = 0; j < 4; j++) {
                int n0 = n + 2*j, n1 = n + 2*j + 1;
                float v0 = w0*f0[n0] + w1*f1[n0] + w2*f2[n0];
                float v1 = w0*f0[n1] + w1*f1[n1] + w2*f2[n1];
                split_bf(v0, Ho.b2[j].x, Lo.b2[j].x);
                split_bf(v1, Ho.b2[j].y, Lo.b2[j].y);
            }
            size_t idx = (size_t)o*M_ + colbase + n;
            *(uint4*)&g_X0h[idx] = Ho.u;
            *(uint4*)&g_X0l[idx] = Lo.u;
        }
    }
}

// ---------------- 3. ALL weight prep in one launch ----------------
__global__ void wprep_kernel(const float* __restrict__ Wd0s, const float* __restrict__ Wss,
                             const float* __restrict__ W0s, const float* __restrict__ Wd1s,
                             const float* __restrict__ W1s) {
    int idx = blockIdx.x * 256 + threadIdx.x;
    const int R0 = 5*384*C2;            // 491520
    const int R1 = R0 + 5*H3*C2;        // 655360
    const int R2 = R1 + 5*H3*H3;        // 737280
    bf16 h, l;
    if (idx < R0) {
        int i   = idx / (384*C2);
        int rem = idx % (384*C2);
        int r = rem / C2, c = rem % C2;
        float v = (r < C2) ? Wd0s[(size_t)i*C2*C2 + r*C2 + c]
                           : Wss [(size_t)i*H3*C2 + (r - C2)*C2 + c];
        g_Wcat[idx] = v;
        split_bf(v, h, l);
        g_WcatH[idx] = h; g_WcatL[idx] = l;
    } else if (idx < R1) {
        int j = idx - R0;
        split_bf(W0s[j], h, l);  g_W0H[j] = h;  g_W0L[j] = l;
    } else if (idx < R2) {
        int j = idx - R1;
        split_bf(Wd1s[j], h, l); g_Wd1H[j] = h; g_Wd1L[j] = l;
    } else {
        int j = idx - R2;
        split_bf(W1s[j], h, l);  g_W1H[j] = h;  g_W1L[j] = l;
    }
}

// ---------------- 3d. Badd[384][24] = Wcat[:,128:] @ P ----------------
__global__ void badd_kernel(const float* __restrict__ Wcat) {
    int idx = blockIdx.x * 256 + threadIdx.x;   // 9216
    if (idx >= 384*24) return;
    int r = idx / 24, cg = idx % 24;
    float s = 0.f;
#pragma unroll 8
    for (int k = 0; k < H3; k++)
        s += Wcat[r*C2 + H3 + k] * g_P[k*24 + cg];
    g_Badd[idx] = s;
}

// ---------------- 4. bf16x3 GEMM, 128x128 tile, 3-stage dynamic-smem pipeline --------
// One __syncthreads per stage: after sync, issue cp.async into (s+2)%3 while
// consuming buffer s%3. Stage smem = A hi/lo 8KB + B hi/lo 8.5KB -> 3 stages 49.5KB.
__global__ __launch_bounds__(256, 2)
void gemm_bfx3_kernel(const bf16* __restrict__ Ah, const bf16* __restrict__ Al, int lda,
                      const bf16* __restrict__ Bh, const bf16* __restrict__ Bl,
                      float* __restrict__ Yf, bf16* __restrict__ Yh, bf16* __restrict__ Yl,
                      int K, const float* __restrict__ Badd, const float* __restrict__ Add,
                      float* __restrict__ Psum)
{
    const int SA = 16, SB = 136;
    const int ASZ = 128*SA;            // 2048 elems = 4KB per plane
    const int BSZ = 16*SB;             // 2176 elems = 4.25KB per plane
    extern __shared__ bf16 smem[];
    bf16* sAh = smem;                  // [3][ASZ]
    bf16* sAl = sAh + 3*ASZ;
    bf16* sBh = sAl + 3*ASZ;           // [3][BSZ]
    bf16* sBl = sBh + 3*BSZ;

    int tid = threadIdx.x, lane = tid & 31, wid = tid >> 5;
    int warp_m = wid >> 2, warp_n = wid & 3;
    int gid = lane >> 2, tig = lane & 3;
    int nBase = blockIdx.x * 128, oBase = blockIdx.y * 128;

    int aRow = tid >> 1, aG = tid & 1;
    const bf16* Agh = Ah + (size_t)(oBase + aRow)*lda + aG*8;
    const bf16* Agl = Al + (size_t)(oBase + aRow)*lda + aG*8;
    int aOffSm = aRow*SA + ((aG ^ ((aRow >> 2) & 1)) << 3);

    const bool bHi = (tid < 128);
    int bs   = tid & 127;
    int bRow = bs >> 4, bC = (bs & 15) * 8;
    const bf16* Bg = (bHi ? Bh : Bl) + (size_t)bRow*M_ + nBase + bC;
    int bOff0 = bRow*SB + bC;
    int bOff1 = (bRow + 8)*SB + bC;

    int selA = ((lane >> 3) & 1) * 8 + (lane & 7);
    int halfA = lane >> 4;
    uint32_t aOff[4];
#pragma unroll
    for (int mt = 0; mt < 4; mt++) {
        int row = warp_m*64 + mt*16 + selA;
        aOff[mt] = (uint32_t)((row*SA + ((halfA ^ ((row >> 2) & 1)) << 3)) * 2);
    }
    int selBk = ((lane >> 3) & 1) * 8 + (lane & 7);
    int selBn = (lane >> 4) * 8;
    uint32_t bOff[2];
#pragma unroll
    for (int j = 0; j < 2; j++)
        bOff[j] = (uint32_t)((selBk*SB + warp_n*32 + j*16 + selBn) * 2);

    uint32_t sAhB = scvt(sAh), sAlB = scvt(sAl), sBhB = scvt(sBh), sBlB = scvt(sBl);

    int stages = K >> 4;
    float c[4][4][4];
#pragma unroll
    for (int mt = 0; mt < 4; mt++)
#pragma unroll
        for (int nt = 0; nt < 4; nt++)
#pragma unroll
            for (int r = 0; r < 4; r++) c[mt][nt][r] = 0.f;

#define LOAD_STAGE(s, buf)                                              \
    do {                                                                \
        int k0_ = (s) * 16;                                             \
        cp16g(sAh + (buf)*ASZ + aOffSm, Agh + k0_);                     \
        cp16g(sAl + (buf)*ASZ + aOffSm, Agl + k0_);                     \
        bf16* bdst = (bHi ? sBh : sBl) + (buf)*BSZ;                     \
        cp16g(bdst + bOff0, Bg + (size_t)k0_*M_);                       \
        cp16g(bdst + bOff1, Bg + (size_t)(k0_ + 8)*M_);                 \
        asm volatile("cp.async.commit_group;");                         \
    } while (0)

    LOAD_STAGE(0, 0);
    if (stages > 1) LOAD_STAGE(1, 1);

    for (int s = 0; s < stages; s++) {
        if (s == stages - 1) asm volatile("cp.async.wait_group 0;");
        else                 asm volatile("cp.async.wait_group 1;");
        __syncthreads();
        int buf = s % 3;
        if (s + 2 < stages) LOAD_STAGE(s + 2, (s + 2) % 3);

        uint32_t aBh = sAhB + buf*ASZ*2, aBl = sAlB + buf*ASZ*2;
        uint32_t bBh = sBhB + buf*BSZ*2, bBl = sBlB + buf*BSZ*2;

        uint32_t bh[2][4], bl[2][4];
        ldsm4t(bh[0], bBh + bOff[0]);
        ldsm4t(bh[1], bBh + bOff[1]);
        ldsm4t(bl[0], bBl + bOff[0]);
        ldsm4t(bl[1], bBl + bOff[1]);

#pragma unroll
        for (int h2 = 0; h2 < 2; h2++) {
            uint32_t ah[2][4], al[2][4];
            ldsm4(ah[0], aBh + aOff[h2*2]);
            ldsm4(ah[1], aBh + aOff[h2*2 + 1]);
            ldsm4(al[0], aBl + aOff[h2*2]);
            ldsm4(al[1], aBl + aOff[h2*2 + 1]);
#pragma unroll
            for (int m2 = 0; m2 < 2; m2++)
#pragma unroll
                for (int nt = 0; nt < 4; nt++) {
                    const uint32_t* bhf = &bh[nt >> 1][(nt & 1)*2];
                    const uint32_t* blf = &bl[nt >> 1][(nt & 1)*2];
                    float* cc = c[h2*2 + m2][nt];
                    mma16(cc, ah[m2], bhf);   // hi*hi
                    mma16(cc, ah[m2], blf);   // hi*lo
                    mma16(cc, al[m2], bhf);   // lo*hi
                }
        }
    }
#undef LOAD_STAGE

    int cg = nBase >> 10;
    float ps0[4] = {0.f, 0.f, 0.f, 0.f}, ps1[4] = {0.f, 0.f, 0.f, 0.f};
#pragma unroll
    for (int mt = 0; mt < 4; mt++) {
#pragma unroll
        for (int nt = 0; nt < 4; nt++) {
            int r0 = oBase + warp_m*64 + mt*16 + gid;
            int r1 = r0 + 8;
            int col = nBase + warp_n*32 + nt*8 + tig*2;
            float* cc = c[mt][nt];
            float ba0 = 0.f, ba1 = 0.f;
            if (Badd) { ba0 = Badd[r0*24 + cg]; ba1 = Badd[r1*24 + cg]; }
            size_t p0 = (size_t)r0*M_ + col;
            size_t p1 = (size_t)r1*M_ + col;
            float o0 = cc[0] + ba0, o1 = cc[1] + ba0;
            float o2 = cc[2] + ba1, o3 = cc[3] + ba1;
            if (Add) {
                float2 t0 = *(const float2*)&Add[p0];
                float2 t1 = *(const float2*)&Add[p1];
                o0 += t0.x; o1 += t0.y; o2 += t1.x; o3 += t1.y;
            }
            ps0[mt] += o0 + o1;
            ps1[mt] += o2 + o3;
            if (Yf) {
                *(float2*)&Yf[p0] = make_float2(o0, o1);
                *(float2*)&Yf[p1] = make_float2(o2, o3);
            } else {
                __nv_bfloat162 h0, l0, h1, l1;
                split_bf(o0, h0.x, l0.x); split_bf(o1, h0.y, l0.y);
                split_bf(o2, h1.x, l1.x); split_bf(o3, h1.y, l1.y);
                *(__nv_bfloat162*)&Yh[p0] = h0;
                *(__nv_bfloat162*)&Yl[p0] = l0;
                *(__nv_bfloat162*)&Yh[p1] = h1;
                *(__nv_bfloat162*)&Yl[p1] = l1;
            }
        }
    }
    if (Psum) {
        const float invN = 1.f / N_;
#pragma unroll
        for (int mt = 0; mt < 4; mt++) {
            float a = ps0[mt], b2 = ps1[mt];
            a  += __shfl_xor_sync(0xffffffffu, a, 1);
            a  += __shfl_xor_sync(0xffffffffu, a, 2);
            b2 += __shfl_xor_sync(0xffffffffu, b2, 1);
            b2 += __shfl_xor_sync(0xffffffffu, b2, 2);
            if (tig == 0) {
                int r0 = oBase + warp_m*64 + mt*16 + gid;
                atomicAdd(&Psum[r0*24 + cg], a * invN);
                atomicAdd(&Psum[(r0 + 8)*24 + cg], b2 * invN);
            }
        }
    }
}

// ---------------- 5. VN leaky-relu, 8-wide vectorized ----------------
__global__ void lrelu_kernel(const bf16* __restrict__ Xh, const bf16* __restrict__ Xl,
                             const float* __restrict__ P, const float* __restrict__ Dsrc,
                             bf16* __restrict__ Dh, bf16* __restrict__ Dl,
                             float* __restrict__ Pzero) {
    int idx = blockIdx.x * 256 + threadIdx.x;
    if (Pzero && idx < H3*24) Pzero[idx] = 0.f;
    int n = (idx & 127) * 8;
    int b = (idx >> 7) & 7;
    int c = idx >> 10;
    size_t base = (size_t)c*M_ + (size_t)b*3*N_ + n;

    float x[3][8], d[3][8];
#pragma unroll
    for (int v = 0; v < 3; v++) {
        size_t o = base + (size_t)v*N_;
        if (P != nullptr && c >= H3) {
            float xv = P[(c - H3)*24 + b*3 + v];
#pragma unroll
            for (int j = 0; j < 8; j++) x[v][j] = xv;
        } else {
            union { uint4 u; __nv_bfloat162 b2[4]; } Hd, Ld;
            Hd.u = *(const uint4*)&Xh[o];
            Ld.u = *(const uint4*)&Xl[o];
#pragma unroll
            for (int j = 0; j < 4; j++) {
                x[v][2*j]   = __bfloat162float(Hd.b2[j].x) + __bfloat162float(Ld.b2[j].x);
                x[v][2*j+1] = __bfloat162float(Hd.b2[j].y) + __bfloat162float(Ld.b2[j].y);
            }
        }
        float4 d0 = *(const float4*)&Dsrc[o];
        float4 d1 = *(const float4*)&Dsrc[o + 4];
        d[v][0] = d0.x; d[v][1] = d0.y; d[v][2] = d0.z; d[v][3] = d0.w;
        d[v][4] = d1.x; d[v][5] = d1.y; d[v][6] = d1.z; d[v][7] = d1.w;
    }
#pragma unroll
    for (int j = 0; j < 8; j++) {
        float dot = x[0][j]*d[0][j] + x[1][j]*d[1][j] + x[2][j]*d[2][j];
        if (dot < 0.f) {
            float dd = d[0][j]*d[0][j] + d[1][j]*d[1][j] + d[2][j]*d[2][j];
            float s = dot / (dd + EPSF);
            x[0][j] -= s*d[0][j]; x[1][j] -= s*d[1][j]; x[2][j] -= s*d[2][j];
        }
    }
#pragma unroll
    for (int v = 0; v < 3; v++) {
        size_t o = base + (size_t)v*N_;
        union { uint4 u; __nv_bfloat162 b2[4]; } Ho, Lo;
#pragma unroll
        for (int j = 0; j < 4; j++) {
            split_bf(x[v][2*j],   Ho.b2[j].x, Lo.b2[j].x);
            split_bf(x[v][2*j+1], Ho.b2[j].y, Lo.b2[j].y);
        }
        *(uint4*)&Dh[o] = Ho.u;
        *(uint4*)&Dl[o] = Lo.u;
    }
}

// ---------------- 7. head ----------------
__global__ void final_kernel(const float* __restrict__ Wd, const float* __restrict__ Wc,
                             float* __restrict__ out) {
    __shared__ float s_net[H3*24];
    __shared__ float s_act[H3*24];
    int o = threadIdx.x;
    for (int t = o; t < H3*24; t += 128) s_net[t] = g_P[t];
    __syncthreads();

    float dcol[24];
#pragma unroll
    for (int col = 0; col < 24; col++) dcol[col] = 0.f;
    for (int i = 0; i < H3; i++) {
        float w = Wd[o*H3 + i];
#pragma unroll
        for (int col = 0; col < 24; col++) dcol[col] += w * s_net[i*24 + col];
    }
#pragma unroll
    for (int b = 0; b < 8; b++) {
        float x0 = s_net[o*24 + b*3], x1 = s_net[o*24 + b*3 + 1], x2 = s_net[o*24 + b*3 + 2];
        float d0 = dcol[b*3], d1 = dcol[b*3 + 1], d2 = dcol[b*3 + 2];
        float dot = x0*d0 + x1*d1 + x2*d2;
        float a0 = x0, a1 = x1, a2 = x2;
        if (dot < 0.f) {
            float dd = d0*d0 + d1*d1 + d2*d2;
            float s = dot / (dd + EPSF);
            a0 = x0 - s*d0; a1 = x1 - s*d1; a2 = x2 - s*d2;
        }
        s_act[o*24 + b*3] = a0; s_act[o*24 + b*3 + 1] = a1; s_act[o*24 + b*3 + 2] = a2;
    }
    __syncthreads();

    float oc[24];
#pragma unroll
    for (int col = 0; col < 24; col++) oc[col] = 0.f;
    for (int i = 0; i < H3; i++) {
        float w = Wc[o*H3 + i];
#pragma unroll
        for (int col = 0; col < 24; col++) oc[col] += w * s_act[i*24 + col];
    }
#pragma unroll
    for (int col = 0; col < 24; col++) {
        int b = col / 3, v = col % 3;
        out[b*384 + o*3 + v] = oc[col];
    }
}

// ---------------- host ----------------
static float* symaddrf(const void* sym) {
    void* p = nullptr; cudaGetSymbolAddress(&p, sym); return (float*)p;
}
static bf16* symaddrb(const void* sym) {
    void* p = nullptr; cudaGetSymbolAddress(&p, sym); return (bf16*)p;
}

#define GEMM_SMEM (3*(128*16 + 16*136)*2*2)   // 3 stages * (A + B) * hi/lo * 2B = 50688

extern "C" void kernel_launch(void* const* d_in, const int* in_sizes, int n_in,
                              void* d_out, int out_size) {
    const float* p      = (const float*)d_in[0];
    const float* Wpos   = (const float*)d_in[1];
    const float* Wd0s   = (const float*)d_in[2];
    const float* W0s    = (const float*)d_in[3];
    const float* Wd1s   = (const float*)d_in[4];
    const float* W1s    = (const float*)d_in[5];
    const float* Wss    = (const float*)d_in[6];
    const float* Wd_act = (const float*)d_in[7];
    const float* Wc     = (const float*)d_in[8];
    float* out = (float*)d_out;

    static bool s_attr = false;
    if (!s_attr) {
        cudaFuncSetAttribute(gemm_bfx3_kernel,
                             cudaFuncAttributeMaxDynamicSharedMemorySize, GEMM_SMEM);
        s_attr = true;
    }

    float* DS    = symaddrf(g_DS);
    float* S     = DS + (size_t)C2*M_;
    float* D1    = symaddrf(g_D1);
    float* Wcat  = symaddrf(g_Wcat);
    float* Badd  = symaddrf(g_Badd);
    float* P     = symaddrf(g_P);
    bf16 *X0h = symaddrb(g_X0h), *X0l = symaddrb(g_X0l);
    bf16 *DSh = symaddrb(g_DSh), *DSl = symaddrb(g_DSl);
    bf16 *Nth = symaddrb(g_Nth), *Ntl = symaddrb(g_Ntl);
    bf16 *D1h = symaddrb(g_D1h), *D1l = symaddrb(g_D1l);
    bf16 *WcH = symaddrb(g_WcatH), *WcL = symaddrb(g_WcatL);
    bf16 *W0H = symaddrb(g_W0H),   *W0L = symaddrb(g_W0L);
    bf16 *Wd1H = symaddrb(g_Wd1H), *Wd1L = symaddrb(g_Wd1L);
    bf16 *W1H = symaddrb(g_W1H),   *W1L = symaddrb(g_W1L);

    knn_center_kernel<<<B_*4, 256>>>(p);                     // launch 1
    featpos_kernel<<<24, 256>>>(Wpos);                       // launch 2
    wprep_kernel<<<3200, 256>>>(Wd0s, Wss, W0s, Wd1s, W1s);  // launch 3

    for (int i = 0; i < 5; i++) {
        size_t oc2 = (size_t)i*384*C2;
        const bf16* WciH = WcH + oc2; const bf16* WciL = WcL + oc2;
        const bf16* W0iH = W0H + (size_t)i*H3*C2;   const bf16* W0iL = W0L + (size_t)i*H3*C2;
        const bf16* Wd1iH = Wd1H + (size_t)i*H3*H3; const bf16* Wd1iL = Wd1L + (size_t)i*H3*H3;
        const bf16* W1iH = W1H + (size_t)i*H3*H3;   const bf16* W1iL = W1L + (size_t)i*H3*H3;

        if (i == 0) {
            // D;S = [Wd0;Ws] @ X0  (K=256)            -- launch 4: ncu target
            gemm_bfx3_kernel<<<dim3(192, 3), 256, GEMM_SMEM>>>(WciH, WciL, C2, X0h, X0l,
                DS, nullptr, nullptr, C2, nullptr, nullptr, nullptr);
        } else {
            badd_kernel<<<36, 256>>>(Wcat + oc2);
            gemm_bfx3_kernel<<<dim3(192, 3), 256, GEMM_SMEM>>>(WciH, WciL, C2, X0h, X0l,
                DS, nullptr, nullptr, H3, Badd, nullptr, nullptr);
        }
        // D' = lrelu(X, D) -> pairs
        lrelu_kernel<<<1024, 256>>>(X0h, X0l, (i == 0) ? nullptr : P, DS,
                                    DSh, DSl, nullptr);
        // Nt = W0 @ D'  (K=256) -> pairs
        gemm_bfx3_kernel<<<dim3(192, 1), 256, GEMM_SMEM>>>(W0iH, W0iL, C2, DSh, DSl,
            nullptr, Nth, Ntl, C2, nullptr, nullptr, nullptr);
        // D1 = Wd1 @ Nt (K=128) -> fp32
        gemm_bfx3_kernel<<<dim3(192, 1), 256, GEMM_SMEM>>>(Wd1iH, Wd1iL, H3, Nth, Ntl,
            D1, nullptr, nullptr, H3, nullptr, nullptr, nullptr);
        // D1' = lrelu(Nt, D1) -> pairs; zeroes P for the fused pool below
        lrelu_kernel<<<512, 256>>>(Nth, Ntl, nullptr, D1, D1h, D1l, P);
        // netX = W1 @ D1' + S (K=128) -> pairs into X0; fused pool accumulates P
        gemm_bfx3_kernel<<<dim3(192, 1), 256, GEMM_SMEM>>>(W1iH, W1iL, H3, D1h, D1l,
            nullptr, X0h, X0l, H3, nullptr, S, P);
    }

    final_kernel<<<1, 128>>>(Wd_act, Wc, out);
}